// round 10
// baseline (speedup 1.0000x reference)
#include <cuda_runtime.h>
#include <cuda_fp16.h>
#include <cstddef>
#include <cstdint>

#define NN 100000
#define EE 640000
#define PP 640000
#define DD 128
#define GG 128
#define LL 3
#define BN_EPS 1e-5f

// ---------------- device scratch ----------------
__device__ __half g_z2 [(size_t)EE * DD];            // fp16 z (proven)
__device__ float  g_hin[(size_t)NN * DD];            // fp32 h_in (fp16 twice-falsified)
__device__ float  g_agg[(size_t)NN * DD];            // fp32 (atomic target)
__device__ float  g_t2 [((size_t)NN + 128) * 2 * DD];// tf32-rounded fp32 (+pad for cp.async)
__device__ float  g_vn [GG * DD];
__device__ float  g_vt [GG * DD];
__device__ float  g_wh [262144];                     // tf32-rounded weights
__device__ int    g_st [EE + 1];                     // pos_batch segment starts

#define OFF_ZEW 0
#define OFF_WP(l) (16384 + (l) * 81920)
#define OFF_W1(l) (16384 + (l) * 81920 + 16384)
#define OFF_W2(l) (16384 + (l) * 81920 + 49152)

// ---------------- helpers ----------------
__device__ __forceinline__ void red_add_v4(float* p, float4 v) {
    asm volatile("red.global.add.v4.f32 [%0], {%1,%2,%3,%4};"
                 :: "l"(p), "f"(v.x), "f"(v.y), "f"(v.z), "f"(v.w) : "memory");
}
__device__ __forceinline__ unsigned f2tf(float f) {
    unsigned u;
    asm("cvt.rna.tf32.f32 %0, %1;" : "=r"(u) : "f"(f));
    return u;
}
__device__ __forceinline__ float tf32r(float f) { return __uint_as_float(f2tf(f)); }
__device__ __forceinline__ void mma_tf32(float* c, const unsigned* a, const unsigned* b) {
    asm volatile("mma.sync.aligned.m16n8k8.row.col.f32.tf32.tf32.f32 "
                 "{%0,%1,%2,%3}, {%4,%5,%6,%7}, {%8,%9}, {%0,%1,%2,%3};"
                 : "+f"(c[0]), "+f"(c[1]), "+f"(c[2]), "+f"(c[3])
                 : "r"(a[0]), "r"(a[1]), "r"(a[2]), "r"(a[3]),
                   "r"(b[0]), "r"(b[1]));
}
__device__ __forceinline__ unsigned pack2h(float x, float y) {
    __half2 h = __floats2half2_rn(x, y);
    return *(unsigned*)&h;
}
__device__ __forceinline__ void cp16(void* s, const void* g) {
    unsigned sa = (unsigned)__cvta_generic_to_shared(s);
    asm volatile("cp.async.cg.shared.global [%0], [%1], 16;" :: "r"(sa), "l"(g));
}
__device__ __forceinline__ void cp_commit() {
    asm volatile("cp.async.commit_group;" ::: "memory");
}
__device__ __forceinline__ void cp_wait0() {
    asm volatile("cp.async.wait_group 0;" ::: "memory");
}

#define AS_S 68
#define BS_S 132
#define SM_T64 ((64 * AS_S + 64 * BS_S) * 4)   // 51200 B : A 64x64 chunk + B 64x128 chunk

// tf32 mma inner loop: M-tile 64 (warp 32 rows), N 128, k-chunk 64
#define MMA_CHUNK64(As, Bs, warp_m, warp_n, g, t, acc)                             \
    _Pragma("unroll")                                                              \
    for (int kk = 0; kk < 64; kk += 8) {                                           \
        unsigned af[2][4], bf[4][2];                                               \
        _Pragma("unroll")                                                          \
        for (int mt = 0; mt < 2; mt++) {                                           \
            int mb = (warp_m) * 32 + mt * 16;                                      \
            af[mt][0] = (As)[(mb + (g)) * AS_S + kk + (t)];                        \
            af[mt][1] = (As)[(mb + (g) + 8) * AS_S + kk + (t)];                    \
            af[mt][2] = (As)[(mb + (g)) * AS_S + kk + (t) + 4];                    \
            af[mt][3] = (As)[(mb + (g) + 8) * AS_S + kk + (t) + 4];                \
        }                                                                          \
        _Pragma("unroll")                                                          \
        for (int nt = 0; nt < 4; nt++) {                                           \
            int n = (warp_n) * 32 + nt * 8 + (g);                                  \
            bf[nt][0] = (Bs)[(kk + (t)) * BS_S + n];                               \
            bf[nt][1] = (Bs)[(kk + (t) + 4) * BS_S + n];                           \
        }                                                                          \
        _Pragma("unroll")                                                          \
        for (int mt = 0; mt < 2; mt++)                                             \
            _Pragma("unroll")                                                      \
            for (int nt = 0; nt < 4; nt++)                                         \
                mma_tf32(acc[mt][nt], af[mt], bf[nt]);                             \
    }

// ---------------- prep kernels ----------------
__global__ void k_prep(const float* __restrict__ zeW, const float* __restrict__ Wp,
                       const float* __restrict__ W1, const float* __restrict__ W2,
                       float* __restrict__ wh) {
    int i = blockIdx.x * 256 + threadIdx.x;
    if (i >= 262144) return;
    if (i < 16384) { wh[OFF_ZEW + i] = tf32r(zeW[i]); return; }
    int j = i - 16384;
    int l = j / 81920;
    j = j % 81920;
    if (j < 16384)       wh[OFF_WP(l) + j]           = tf32r(Wp[(size_t)l * 16384 + j]);
    else if (j < 49152)  wh[OFF_W1(l) + (j - 16384)] = tf32r(W1[(size_t)l * 32768 + j - 16384]);
    else                 wh[OFF_W2(l) + (j - 49152)] = tf32r(W2[(size_t)l * 32768 + j - 49152]);
}

__global__ void k_starts(const int* __restrict__ pbatch, int* __restrict__ starts) {
    int p = blockIdx.x * 256 + threadIdx.x;
    if (p > PP) return;
    int prev = (p == 0) ? -1 : __ldg(pbatch + p - 1);
    int cur  = (p == PP) ? EE : __ldg(pbatch + p);
    for (int seg = prev + 1; seg <= cur; seg++) starts[seg] = p;
}

// ---------------- init kernels ----------------
__global__ void k_init_vn(const float* __restrict__ emb, float* __restrict__ vn) {
    int i = blockIdx.x * blockDim.x + threadIdx.x;
    if (i < GG * DD) vn[i] = emb[i & (DD - 1)];
}

__global__ void k_init_hin(const int* __restrict__ xn, const float* __restrict__ emb,
                           const float* __restrict__ vne, const float* __restrict__ epsp,
                           float* __restrict__ hin, float* __restrict__ agg) {
    int i = blockIdx.x * blockDim.x + threadIdx.x;
    if (i >= NN * 32) return;
    int row = i >> 5, q = (i & 31) << 2;
    float c = 1.0f + __ldg(epsp);
    float4 a = *(const float4*)(emb + (size_t)xn[row] * DD + q);
    float4 b = *(const float4*)(vne + q);
    a.x += b.x; a.y += b.y; a.z += b.z; a.w += b.w;
    *(float4*)(hin + (size_t)row * DD + q) = a;
    float4 e = make_float4(c * a.x, c * a.y, c * a.z, c * a.w);
    *(float4*)(agg + (size_t)row * DD + q) = e;
}

// ---------------- fused z-encoder (M-tile 64) ----------------
__global__ __launch_bounds__(256, 3)
void k_zenc(const int* __restrict__ pidx, const float* __restrict__ penc,
            const int* __restrict__ startsg, const float* __restrict__ zinit,
            const float* __restrict__ bn1, const float* __restrict__ zeb,
            const float* __restrict__ bn2, const float* __restrict__ zeWr,
            __half* __restrict__ z2) {
    extern __shared__ unsigned smem[];
    unsigned* As = smem;                 // 64 x AS_S
    unsigned* Bs = smem + 64 * AS_S;     // 64 x BS_S
    __shared__ float sc1[128], sh1[128];

    const int tid = threadIdx.x;
    const int row0 = blockIdx.x * 64;

    if (tid < 128) {
        float s = bn1[tid] * rsqrtf(bn1[3 * 128 + tid] + BN_EPS);
        sc1[tid] = s;
        sh1[tid] = bn1[128 + tid] - bn1[2 * 128 + tid] * s;
    }

    const int lane = tid & 31, wid = tid >> 5;
    const int g = lane >> 2, t = lane & 3;
    const int warp_m = wid & 1, warp_n = wid >> 1;
    const int ar = tid >> 2;            // 0..63 : segment row
    const int cc = (tid & 3) << 4;      // 0,16,32,48 : col slice within chunk

    float acc[2][4][4];
#pragma unroll
    for (int mt = 0; mt < 2; mt++)
#pragma unroll
        for (int nt = 0; nt < 4; nt++)
#pragma unroll
            for (int q = 0; q < 4; q++) acc[mt][nt][q] = 0.f;

    const int st = __ldg(startsg + row0 + ar);
    const int en = __ldg(startsg + row0 + ar + 1);

    for (int k0 = 0; k0 < 128; k0 += 64) {
        __syncthreads();   // previous MMA done with As/Bs
        // B chunk 64x128 via cp.async
#pragma unroll
        for (int i = 0; i < 8; i++) {
            int idx = tid + i * 256;
            int r = idx >> 5, c4 = (idx & 31) << 2;
            cp16(Bs + r * BS_S + c4, zeWr + (size_t)(k0 + r) * 128 + c4);
        }
        cp_commit();
        // A chunk rows via segment-sum: 16 cols per thread
        {
            float4 a[4];
#pragma unroll
            for (int j = 0; j < 4; j++) a[j] = make_float4(0.f, 0.f, 0.f, 0.f);
            for (int p = st; p < en; p++) {
                int zi = __ldg(pidx + p);
                float w = __ldg(penc + p);
                const float* zr = zinit + (size_t)zi * 128 + k0 + cc;
#pragma unroll
                for (int j = 0; j < 4; j++) {
                    float4 v = *(const float4*)(zr + 4 * j);
                    a[j].x += v.x * w; a[j].y += v.y * w; a[j].z += v.z * w; a[j].w += v.w * w;
                }
            }
#pragma unroll
            for (int j = 0; j < 4; j++) {
                int c = cc + 4 * j;
                int gc = k0 + c;
                float y0 = fmaxf(a[j].x * sc1[gc + 0] + sh1[gc + 0], 0.f);
                float y1 = fmaxf(a[j].y * sc1[gc + 1] + sh1[gc + 1], 0.f);
                float y2 = fmaxf(a[j].z * sc1[gc + 2] + sh1[gc + 2], 0.f);
                float y3 = fmaxf(a[j].w * sc1[gc + 3] + sh1[gc + 3], 0.f);
                *(uint4*)(As + ar * AS_S + c) = make_uint4(f2tf(y0), f2tf(y1), f2tf(y2), f2tf(y3));
            }
        }
        cp_wait0();
        __syncthreads();
        MMA_CHUNK64(As, Bs, warp_m, warp_n, g, t, acc)
    }

    float sc[8], sh[8];
#pragma unroll
    for (int nt = 0; nt < 4; nt++)
#pragma unroll
        for (int hh = 0; hh < 2; hh++) {
            int c = warp_n * 32 + nt * 8 + 2 * t + hh;
            float s = bn2[c] * rsqrtf(bn2[3 * 128 + c] + BN_EPS);
            sc[nt * 2 + hh] = s;
            sh[nt * 2 + hh] = bn2[128 + c] + (zeb[c] - bn2[2 * 128 + c]) * s;
        }
#pragma unroll
    for (int mt = 0; mt < 2; mt++)
#pragma unroll
        for (int half = 0; half < 2; half++) {
            int gr = row0 + warp_m * 32 + mt * 16 + g + 8 * half;
#pragma unroll
            for (int nt = 0; nt < 4; nt++) {
                float y0 = fmaxf(acc[mt][nt][half * 2 + 0] * sc[nt * 2 + 0] + sh[nt * 2 + 0], 0.f);
                float y1 = fmaxf(acc[mt][nt][half * 2 + 1] * sc[nt * 2 + 1] + sh[nt * 2 + 1], 0.f);
                int cb = warp_n * 32 + nt * 8 + 2 * t;
                *(unsigned*)(z2 + (size_t)gr * 128 + cb) = pack2h(y0, y1);
            }
        }
}

// ---------------- fused edge GEMM + gather + scatter (M-tile 64) ----------------
__global__ __launch_bounds__(256, 3)
void k_edge_fused(const __half* __restrict__ z2, const float* __restrict__ Wpr,
                  const float* __restrict__ bp, const float* __restrict__ be,
                  const float* __restrict__ Ae, const float* __restrict__ We7,
                  const int* __restrict__ src, const int* __restrict__ dst,
                  const float* __restrict__ hin, float* __restrict__ agg) {
    extern __shared__ unsigned smem[];
    unsigned* As = smem;
    unsigned* Bs = smem + 64 * AS_S;
    float* eeS = (float*)smem;              // [64][132], aliases As..Bs region
    __shared__ float AeS[64 * 8];
    __shared__ float WeS[7 * 128];

    const int tid = threadIdx.x;
    const int row0 = blockIdx.x * 64;

    for (int i = tid; i < 64 * 7; i += 256) {
        int r = i / 7, c = i % 7;
        AeS[r * 8 + c] = Ae[(size_t)(row0 + r) * 7 + c];
    }
    for (int i = tid; i < 7 * 128; i += 256) WeS[i] = We7[i];

    const int lane = tid & 31, wid = tid >> 5;
    const int g = lane >> 2, t = lane & 3;
    const int warp_m = wid & 1, warp_n = wid >> 1;

    float acc[2][4][4];
#pragma unroll
    for (int mt = 0; mt < 2; mt++)
#pragma unroll
        for (int nt = 0; nt < 4; nt++)
#pragma unroll
            for (int q = 0; q < 4; q++) acc[mt][nt][q] = 0.f;

    for (int k0 = 0; k0 < 128; k0 += 64) {
        __syncthreads();
#pragma unroll
        for (int i = 0; i < 8; i++) {
            int idx = tid + i * 256;
            int r = idx >> 5, c4 = (idx & 31) << 2;
            cp16(Bs + r * BS_S + c4, Wpr + (size_t)(k0 + r) * 128 + c4);
        }
        cp_commit();
        // A chunk from fp16 z2: 4 slots of 4 cols per thread
#pragma unroll
        for (int i = 0; i < 4; i++) {
            int idx = tid + i * 256;
            int r = idx >> 4, c4 = (idx & 15) << 2;
            const __half2* zp = (const __half2*)(z2 + (size_t)(row0 + r) * 128 + k0 + c4);
            float2 f01 = __half22float2(zp[0]);
            float2 f23 = __half22float2(zp[1]);
            *(uint4*)(As + r * AS_S + c4) =
                make_uint4(f2tf(f01.x), f2tf(f01.y), f2tf(f23.x), f2tf(f23.y));
        }
        cp_wait0();
        __syncthreads();
        MMA_CHUNK64(As, Bs, warp_m, warp_n, g, t, acc)
    }
    __syncthreads();   // done with As/Bs before aliasing as eeS

    float bsum[8];
#pragma unroll
    for (int nt = 0; nt < 4; nt++)
#pragma unroll
        for (int hh = 0; hh < 2; hh++) {
            int c = warp_n * 32 + nt * 8 + 2 * t + hh;
            bsum[nt * 2 + hh] = bp[c] + be[c];
        }
#pragma unroll
    for (int mt = 0; mt < 2; mt++)
#pragma unroll
        for (int half = 0; half < 2; half++) {
            int lr = warp_m * 32 + mt * 16 + g + 8 * half;
            float a7[7];
#pragma unroll
            for (int k = 0; k < 7; k++) a7[k] = AeS[lr * 8 + k];
#pragma unroll
            for (int nt = 0; nt < 4; nt++) {
                int cb = warp_n * 32 + nt * 8 + 2 * t;
                float y0 = acc[mt][nt][half * 2 + 0] + bsum[nt * 2 + 0];
                float y1 = acc[mt][nt][half * 2 + 1] + bsum[nt * 2 + 1];
#pragma unroll
                for (int k = 0; k < 7; k++) {
                    y0 = fmaf(a7[k], WeS[k * 128 + cb], y0);
                    y1 = fmaf(a7[k], WeS[k * 128 + cb + 1], y1);
                }
                *(float2*)(eeS + lr * 132 + cb) = make_float2(y0, y1);
            }
        }
    __syncthreads();

    // gather + relu + scatter: 8 edges per warp
#pragma unroll 4
    for (int i = 0; i < 8; i++) {
        int lr = wid * 8 + i;
        int e = row0 + lr;
        int s = __ldg(src + e), d = __ldg(dst + e);
        float4 ev = *(float4*)(eeS + lr * 132 + lane * 4);
        float4 hv = *(const float4*)(hin + (size_t)s * 128 + lane * 4);
        float4 m;
        m.x = fmaxf(hv.x + ev.x, 0.f);
        m.y = fmaxf(hv.y + ev.y, 0.f);
        m.z = fmaxf(hv.z + ev.z, 0.f);
        m.w = fmaxf(hv.w + ev.w, 0.f);
        red_add_v4(agg + (size_t)d * 128 + lane * 4, m);
    }
}

// ---------------- W1 GEMM (M-tile 64): t2 = tf32r(relu(bn(agg @ W1 + b1))) ----------------
__global__ __launch_bounds__(256, 3)
void tgemm_w1(const float* __restrict__ A, const float* __restrict__ W1r,
              int M, const float* __restrict__ bias, const float* __restrict__ bn,
              float* __restrict__ C) {
    extern __shared__ unsigned smem[];
    unsigned* As = smem;
    unsigned* Bs = smem + 64 * AS_S;
    const int tid = threadIdx.x;
    const int lane = tid & 31, wid = tid >> 5;
    const int g = lane >> 2, t = lane & 3;
    const int warp_m = wid & 1, warp_n = wid >> 1;
    const int row0 = blockIdx.x * 64;
    const int col0 = blockIdx.y * 128;
    const int Nc = 256;

    float acc[2][4][4];
#pragma unroll
    for (int mt = 0; mt < 2; mt++)
#pragma unroll
        for (int nt = 0; nt < 4; nt++)
#pragma unroll
            for (int q = 0; q < 4; q++) acc[mt][nt][q] = 0.f;

    for (int k0 = 0; k0 < 128; k0 += 64) {
        __syncthreads();
#pragma unroll
        for (int i = 0; i < 8; i++) {
            int idx = tid + i * 256;
            int r = idx >> 5, c4 = (idx & 31) << 2;
            cp16(Bs + r * BS_S + c4, W1r + (size_t)(k0 + r) * Nc + col0 + c4);
        }
        cp_commit();
#pragma unroll
        for (int i = 0; i < 4; i++) {
            int idx = tid + i * 256;
            int r = idx >> 4, c4 = (idx & 15) << 2;
            int gr = row0 + r;
            float4 v = make_float4(0.f, 0.f, 0.f, 0.f);
            if (gr < M) v = *(const float4*)(A + (size_t)gr * 128 + k0 + c4);
            *(uint4*)(As + r * AS_S + c4) = make_uint4(f2tf(v.x), f2tf(v.y), f2tf(v.z), f2tf(v.w));
        }
        cp_wait0();
        __syncthreads();
        MMA_CHUNK64(As, Bs, warp_m, warp_n, g, t, acc)
    }

    float sc[8], sh[8];
#pragma unroll
    for (int nt = 0; nt < 4; nt++)
#pragma unroll
        for (int hh = 0; hh < 2; hh++) {
            int c = col0 + warp_n * 32 + nt * 8 + 2 * t + hh;
            float s = bn[c] * rsqrtf(bn[3 * Nc + c] + BN_EPS);
            sc[nt * 2 + hh] = s;
            sh[nt * 2 + hh] = bn[Nc + c] + (bias[c] - bn[2 * Nc + c]) * s;
        }
#pragma unroll
    for (int mt = 0; mt < 2; mt++)
#pragma unroll
        for (int half = 0; half < 2; half++) {
            int gr = row0 + warp_m * 32 + mt * 16 + g + 8 * half;
            if (gr >= M) continue;
#pragma unroll
            for (int nt = 0; nt < 4; nt++) {
                float y0 = fmaxf(acc[mt][nt][half * 2 + 0] * sc[nt * 2 + 0] + sh[nt * 2 + 0], 0.f);
                float y1 = fmaxf(acc[mt][nt][half * 2 + 1] * sc[nt * 2 + 1] + sh[nt * 2 + 1], 0.f);
                int cb = warp_n * 32 + nt * 8 + 2 * t;
                *(float2*)(C + (size_t)gr * Nc + col0 + cb) = make_float2(tf32r(y0), tf32r(y1));
            }
        }
}

// ---------------- W2 GEMM (M-tile 64, K=256) + fused next-layer epilogue ----------------
__global__ __launch_bounds__(256, 3)
void tgemm_w2(const float* __restrict__ A, const float* __restrict__ W2r,
              int M, const float* __restrict__ bias, const float* __restrict__ bn,
              int final_, float* __restrict__ Cf,
              const float* __restrict__ vnext, const int* __restrict__ batch,
              const float* __restrict__ epsp,
              float* __restrict__ hin, float* __restrict__ agg) {
    extern __shared__ unsigned smem[];
    unsigned* As = smem;
    unsigned* Bs = smem + 64 * AS_S;
    const int tid = threadIdx.x;
    const int lane = tid & 31, wid = tid >> 5;
    const int g = lane >> 2, t = lane & 3;
    const int warp_m = wid & 1, warp_n = wid >> 1;
    const int row0 = blockIdx.x * 64;

    float acc[2][4][4];
#pragma unroll
    for (int mt = 0; mt < 2; mt++)
#pragma unroll
        for (int nt = 0; nt < 4; nt++)
#pragma unroll
            for (int q = 0; q < 4; q++) acc[mt][nt][q] = 0.f;

    for (int k0 = 0; k0 < 256; k0 += 64) {
        __syncthreads();
#pragma unroll
        for (int i = 0; i < 4; i++) {
            int idx = tid + i * 256;
            int r = idx >> 4, c4 = (idx & 15) << 2;
            cp16(As + r * AS_S + c4, A + (size_t)(row0 + r) * 256 + k0 + c4);
        }
#pragma unroll
        for (int i = 0; i < 8; i++) {
            int idx = tid + i * 256;
            int r = idx >> 5, c4 = (idx & 31) << 2;
            cp16(Bs + r * BS_S + c4, W2r + (size_t)(k0 + r) * 128 + c4);
        }
        cp_commit();
        cp_wait0();
        __syncthreads();
        MMA_CHUNK64(As, Bs, warp_m, warp_n, g, t, acc)
    }

    float sc[8], sh[8];
#pragma unroll
    for (int nt = 0; nt < 4; nt++)
#pragma unroll
        for (int hh = 0; hh < 2; hh++) {
            int c = warp_n * 32 + nt * 8 + 2 * t + hh;
            float s = bn[c] * rsqrtf(bn[3 * 128 + c] + BN_EPS);
            sc[nt * 2 + hh] = s;
            sh[nt * 2 + hh] = bn[128 + c] + (bias[c] - bn[2 * 128 + c]) * s;
        }

    float ceps = final_ ? 0.f : (1.0f + __ldg(epsp));
#pragma unroll
    for (int mt = 0; mt < 2; mt++)
#pragma unroll
        for (int half = 0; half < 2; half++) {
            int gr = row0 + warp_m * 32 + mt * 16 + g + 8 * half;
            if (gr >= M) continue;
            if (final_) {
#pragma unroll
                for (int nt = 0; nt < 4; nt++) {
                    float y0 = acc[mt][nt][half * 2 + 0] * sc[nt * 2 + 0] + sh[nt * 2 + 0];
                    float y1 = acc[mt][nt][half * 2 + 1] * sc[nt * 2 + 1] + sh[nt * 2 + 1];
                    int cb = warp_n * 32 + nt * 8 + 2 * t;
                    *(float2*)(Cf + (size_t)gr * 128 + cb) = make_float2(y0, y1);
                }
            } else {
                int b = __ldg(batch + gr);
                const float* vrow = vnext + (size_t)b * 128;
#pragma unroll
                for (int nt = 0; nt < 4; nt++) {
                    int cb = warp_n * 32 + nt * 8 + 2 * t;
                    float y0 = fmaxf(acc[mt][nt][half * 2 + 0] * sc[nt * 2 + 0] + sh[nt * 2 + 0], 0.f);
                    float y1 = fmaxf(acc[mt][nt][half * 2 + 1] * sc[nt * 2 + 1] + sh[nt * 2 + 1], 0.f);
                    float h0 = y0 + __ldg(vrow + cb);
                    float h1 = y1 + __ldg(vrow + cb + 1);
                    *(float2*)(hin + (size_t)gr * 128 + cb) = make_float2(h0, h1);
                    *(float2*)(agg + (size_t)gr * 128 + cb) = make_float2(ceps * h0, ceps * h1);
                }
            }
        }
}

// ---------------- virtual node ----------------
__global__ void k_vn_agg(const float* __restrict__ hin, const int* __restrict__ batch,
                         const float* __restrict__ vn, float* __restrict__ vt) {
    int g = blockIdx.x, c = threadIdx.x;
    int lo = 0, hi = NN;
    while (lo < hi) { int m = (lo + hi) >> 1; if (batch[m] < g) lo = m + 1; else hi = m; }
    int start = lo;
    lo = start; hi = NN;
    while (lo < hi) { int m = (lo + hi) >> 1; if (batch[m] < g + 1) lo = m + 1; else hi = m; }
    int end = lo;
    float sum = 0.f;
    for (int i = start; i < end; i++) sum += hin[(size_t)i * DD + c];
    vt[g * DD + c] = sum + vn[g * DD + c];
}

__global__ void k_vn_mlp(const float* __restrict__ vt,
                         const float* __restrict__ W1, const float* __restrict__ b1,
                         const float* __restrict__ bn1,
                         const float* __restrict__ W2, const float* __restrict__ b2,
                         const float* __restrict__ bn2, float* __restrict__ vn) {
    __shared__ float xr[DD];
    __shared__ float tr[2 * DD];
    int g = blockIdx.x, tid = threadIdx.x;
    if (tid < DD) xr[tid] = vt[g * DD + tid];
    __syncthreads();
    float acc = b1[tid];
#pragma unroll 8
    for (int k = 0; k < DD; k++) acc = fmaf(xr[k], W1[(size_t)k * 2 * DD + tid], acc);
    float s = bn1[tid] * rsqrtf(bn1[3 * 2 * DD + tid] + BN_EPS);
    acc = (acc - bn1[2 * 2 * DD + tid]) * s + bn1[2 * DD + tid];
    tr[tid] = fmaxf(acc, 0.f);
    __syncthreads();
    if (tid < DD) {
        float a2 = b2[tid];
#pragma unroll 8
        for (int k = 0; k < 2 * DD; k++) a2 = fmaf(tr[k], W2[(size_t)k * DD + tid], a2);
        float s2 = bn2[tid] * rsqrtf(bn2[3 * DD + tid] + BN_EPS);
        a2 = (a2 - bn2[2 * DD + tid]) * s2 + bn2[DD + tid];
        vn[g * DD + tid] = fmaxf(a2, 0.f);
    }
}

// ---------------- host launcher ----------------
extern "C" void kernel_launch(void* const* d_in, const int* in_sizes, int n_in,
                              void* d_out, int out_size) {
    const int*   x_node     = (const int*)d_in[0];
    const int*   edge_index = (const int*)d_in[1];
    const float* edge_attr  = (const float*)d_in[2];
    const int*   batch      = (const int*)d_in[3];
    const int*   pos_index  = (const int*)d_in[4];
    const float* pos_enc    = (const float*)d_in[5];
    const int*   pos_batch  = (const int*)d_in[6];
    const float* node_emb   = (const float*)d_in[7];
    const float* z_init     = (const float*)d_in[8];
    const float* ze_bn1     = (const float*)d_in[9];
    const float* ze_W       = (const float*)d_in[10];
    const float* ze_b       = (const float*)d_in[11];
    const float* ze_bn2     = (const float*)d_in[12];
    const float* vn_emb     = (const float*)d_in[13];
    const float* conv_We    = (const float*)d_in[14];
    const float* conv_be    = (const float*)d_in[15];
    const float* conv_Wp    = (const float*)d_in[16];
    const float* conv_bp    = (const float*)d_in[17];
    const float* conv_W1    = (const float*)d_in[18];
    const float* conv_b1    = (const float*)d_in[19];
    const float* conv_bn    = (const float*)d_in[20];
    const float* conv_W2    = (const float*)d_in[21];
    const float* conv_b2    = (const float*)d_in[22];
    const float* conv_eps   = (const float*)d_in[23];
    const float* layer_bn   = (const float*)d_in[24];
    const float* vn_W1      = (const float*)d_in[25];
    const float* vn_b1      = (const float*)d_in[26];
    const float* vn_bn1     = (const float*)d_in[27];
    const float* vn_W2      = (const float*)d_in[28];
    const float* vn_b2      = (const float*)d_in[29];
    const float* vn_bn2     = (const float*)d_in[30];

    __half* z2;
    float *hin, *agg, *t2, *vn, *vt, *wh;
    int* sts;
    cudaGetSymbolAddress((void**)&z2,  g_z2);
    cudaGetSymbolAddress((void**)&hin, g_hin);
    cudaGetSymbolAddress((void**)&agg, g_agg);
    cudaGetSymbolAddress((void**)&t2,  g_t2);
    cudaGetSymbolAddress((void**)&vn,  g_vn);
    cudaGetSymbolAddress((void**)&vt,  g_vt);
    cudaGetSymbolAddress((void**)&wh,  g_wh);
    cudaGetSymbolAddress((void**)&sts, g_st);

    cudaFuncSetAttribute(k_zenc, cudaFuncAttributeMaxDynamicSharedMemorySize, SM_T64);
    cudaFuncSetAttribute(k_edge_fused, cudaFuncAttributeMaxDynamicSharedMemorySize, SM_T64);
    cudaFuncSetAttribute(tgemm_w1, cudaFuncAttributeMaxDynamicSharedMemorySize, SM_T64);
    cudaFuncSetAttribute(tgemm_w2, cudaFuncAttributeMaxDynamicSharedMemorySize, SM_T64);

    float* h = (float*)d_out;

    k_prep<<<1024, 256>>>(ze_W, conv_Wp, conv_W1, conv_W2, wh);
    k_starts<<<(PP + 256) / 256, 256>>>(pos_batch, sts);
    k_init_vn<<<(GG * DD + 255) / 256, 256>>>(vn_emb, vn);
    k_init_hin<<<(NN * 32 + 255) / 256, 256>>>(x_node, node_emb, vn_emb, conv_eps, hin, agg);
    k_zenc<<<EE / 64, 256, SM_T64>>>(pos_index, pos_enc, sts, z_init,
                                     ze_bn1, ze_b, ze_bn2, wh + OFF_ZEW, z2);

    const int* srcp = edge_index;
    const int* dstp = edge_index + EE;
    const int nblk64 = (NN + 63) / 64;

    for (int l = 0; l < LL; l++) {
        k_edge_fused<<<EE / 64, 256, SM_T64>>>(z2, wh + OFF_WP(l),
                                               conv_bp + l * DD, conv_be + l * DD,
                                               edge_attr, conv_We + (size_t)l * 7 * DD,
                                               srcp, dstp, hin, agg);
        if (l < LL - 1) {
            k_vn_agg<<<GG, DD>>>(hin, batch, vn, vt);
            k_vn_mlp<<<GG, 256>>>(vt, vn_W1 + (size_t)l * DD * 2 * DD, vn_b1 + l * 2 * DD,
                                  vn_bn1 + (size_t)l * 4 * 2 * DD,
                                  vn_W2 + (size_t)l * 2 * DD * DD, vn_b2 + l * DD,
                                  vn_bn2 + (size_t)l * 4 * DD, vn);
        }
        tgemm_w1<<<dim3(nblk64, 2), 256, SM_T64>>>(agg, wh + OFF_W1(l),
                                                   NN, conv_b1 + l * 2 * DD,
                                                   conv_bn + (size_t)l * 4 * 2 * DD, t2);
        int fin = (l == LL - 1) ? 1 : 0;
        tgemm_w2<<<dim3(nblk64, 1), 256, SM_T64>>>(t2, wh + OFF_W2(l),
                                                   NN, conv_b2 + l * DD,
                                                   layer_bn + (size_t)l * 4 * DD,
                                                   fin, h, vn, batch,
                                                   conv_eps + (fin ? l : l + 1),
                                                   hin, agg);
    }
}

// round 11
// speedup vs baseline: 1.0046x; 1.0046x over previous
#include <cuda_runtime.h>
#include <cuda_fp16.h>
#include <cstddef>
#include <cstdint>

#define NN 100000
#define EE 640000
#define PP 640000
#define DD 128
#define GG 128
#define LL 3
#define BN_EPS 1e-5f

// ---------------- device scratch ----------------
__device__ __half g_z2 [(size_t)EE * DD];            // fp16 z, dst-sorted order
__device__ float  g_hin[(size_t)NN * DD];            // fp32
__device__ float  g_agg[(size_t)NN * DD];            // fp32 (atomic target)
__device__ float  g_t2 [((size_t)NN + 128) * 2 * DD];// tf32-rounded fp32 (+pad)
__device__ float  g_vn [GG * DD];
__device__ float  g_vt [GG * DD];
__device__ float  g_wh [262144];                     // tf32-rounded weights
__device__ int    g_st [EE + 1];                     // pos_batch segment starts
// sort-by-dst scratch
__device__ int    g_cnt [NN + 2];
__device__ int    g_offs[NN + 1];
__device__ int    g_ps  [EE];                        // src, sorted order
__device__ int    g_pd  [EE];                        // dst, sorted order
__device__ int    g_einv[EE];                        // original e -> sorted slot
__device__ float  g_eap [(size_t)EE * 7];            // edge_attr, sorted order

#define OFF_ZEW 0
#define OFF_WP(l) (16384 + (l) * 81920)
#define OFF_W1(l) (16384 + (l) * 81920 + 16384)
#define OFF_W2(l) (16384 + (l) * 81920 + 49152)

// ---------------- helpers ----------------
__device__ __forceinline__ void red_add_v4(float* p, float4 v) {
    asm volatile("red.global.add.v4.f32 [%0], {%1,%2,%3,%4};"
                 :: "l"(p), "f"(v.x), "f"(v.y), "f"(v.z), "f"(v.w) : "memory");
}
__device__ __forceinline__ unsigned f2tf(float f) {
    unsigned u;
    asm("cvt.rna.tf32.f32 %0, %1;" : "=r"(u) : "f"(f));
    return u;
}
__device__ __forceinline__ float tf32r(float f) { return __uint_as_float(f2tf(f)); }
__device__ __forceinline__ void mma_tf32(float* c, const unsigned* a, const unsigned* b) {
    asm volatile("mma.sync.aligned.m16n8k8.row.col.f32.tf32.tf32.f32 "
                 "{%0,%1,%2,%3}, {%4,%5,%6,%7}, {%8,%9}, {%0,%1,%2,%3};"
                 : "+f"(c[0]), "+f"(c[1]), "+f"(c[2]), "+f"(c[3])
                 : "r"(a[0]), "r"(a[1]), "r"(a[2]), "r"(a[3]),
                   "r"(b[0]), "r"(b[1]));
}
__device__ __forceinline__ unsigned pack2h(float x, float y) {
    __half2 h = __floats2half2_rn(x, y);
    return *(unsigned*)&h;
}
__device__ __forceinline__ void cp16(void* s, const void* g) {
    unsigned sa = (unsigned)__cvta_generic_to_shared(s);
    asm volatile("cp.async.cg.shared.global [%0], [%1], 16;" :: "r"(sa), "l"(g));
}
__device__ __forceinline__ void cp_commit() {
    asm volatile("cp.async.commit_group;" ::: "memory");
}
__device__ __forceinline__ void cp_wait0() {
    asm volatile("cp.async.wait_group 0;" ::: "memory");
}

#define AS_S 68
#define BS_S 132
#define SM_BIG ((128 * AS_S + 128 * BS_S) * 4)   // 102400 B
#define SM_W2  ((128 * AS_S + 64 * BS_S) * 4)    // 68608 B

#define MMA_CHUNK(As, Bs, warp_m, warp_n, g, t, acc)                               \
    _Pragma("unroll")                                                              \
    for (int kk = 0; kk < 64; kk += 8) {                                           \
        unsigned af[4][4], bf[4][2];                                               \
        _Pragma("unroll")                                                          \
        for (int mt = 0; mt < 4; mt++) {                                           \
            int mb = (warp_m) * 64 + mt * 16;                                      \
            af[mt][0] = (As)[(mb + (g)) * AS_S + kk + (t)];                        \
            af[mt][1] = (As)[(mb + (g) + 8) * AS_S + kk + (t)];                    \
            af[mt][2] = (As)[(mb + (g)) * AS_S + kk + (t) + 4];                    \
            af[mt][3] = (As)[(mb + (g) + 8) * AS_S + kk + (t) + 4];                \
        }                                                                          \
        _Pragma("unroll")                                                          \
        for (int nt = 0; nt < 4; nt++) {                                           \
            int n = (warp_n) * 32 + nt * 8 + (g);                                  \
            bf[nt][0] = (Bs)[(kk + (t)) * BS_S + n];                               \
            bf[nt][1] = (Bs)[(kk + (t) + 4) * BS_S + n];                           \
        }                                                                          \
        _Pragma("unroll")                                                          \
        for (int mt = 0; mt < 4; mt++)                                             \
            _Pragma("unroll")                                                      \
            for (int nt = 0; nt < 4; nt++)                                         \
                mma_tf32(acc[mt][nt], af[mt], bf[nt]);                             \
    }

// ---------------- prep kernels ----------------
__global__ void k_prep(const float* __restrict__ zeW, const float* __restrict__ Wp,
                       const float* __restrict__ W1, const float* __restrict__ W2,
                       float* __restrict__ wh) {
    int i = blockIdx.x * 256 + threadIdx.x;
    if (i >= 262144) return;
    if (i < 16384) { wh[OFF_ZEW + i] = tf32r(zeW[i]); return; }
    int j = i - 16384;
    int l = j / 81920;
    j = j % 81920;
    if (j < 16384)       wh[OFF_WP(l) + j]           = tf32r(Wp[(size_t)l * 16384 + j]);
    else if (j < 49152)  wh[OFF_W1(l) + (j - 16384)] = tf32r(W1[(size_t)l * 32768 + j - 16384]);
    else                 wh[OFF_W2(l) + (j - 49152)] = tf32r(W2[(size_t)l * 32768 + j - 49152]);
}

__global__ void k_starts(const int* __restrict__ pbatch, int* __restrict__ starts) {
    int p = blockIdx.x * 256 + threadIdx.x;
    if (p > PP) return;
    int prev = (p == 0) ? -1 : __ldg(pbatch + p - 1);
    int cur  = (p == PP) ? EE : __ldg(pbatch + p);
    for (int seg = prev + 1; seg <= cur; seg++) starts[seg] = p;
}

// ---------------- counting sort by dst ----------------
__global__ void k_zero_cnt(int* __restrict__ cnt) {
    int i = blockIdx.x * 256 + threadIdx.x;
    if (i <= NN + 1) cnt[i] = 0;
}
__global__ void k_hist(const int* __restrict__ dst, int* __restrict__ cnt) {
    int e = blockIdx.x * 256 + threadIdx.x;
    if (e < EE) atomicAdd(&cnt[__ldg(dst + e) + 1], 1);
}
// single-block inclusive scan over cnt[0..NN] (NN+1 entries)
__global__ void k_scan(int* __restrict__ cnt) {
    __shared__ int tot[1024];
    const int n = NN + 1;
    int tidx = threadIdx.x;
    int per = (n + 1023) / 1024;
    int s = tidx * per;
    int e = min(s + per, n);
    int run = 0;
    for (int i = s; i < e; i++) { run += cnt[i]; cnt[i] = run; }
    tot[tidx] = run;
    __syncthreads();
    for (int off = 1; off < 1024; off <<= 1) {
        int v = (tidx >= off) ? tot[tidx - off] : 0;
        __syncthreads();
        tot[tidx] += v;
        __syncthreads();
    }
    int add = tot[tidx] - run;   // exclusive offset
    for (int i = s; i < e; i++) cnt[i] += add;
}
__global__ void k_copy_offs(const int* __restrict__ cnt, int* __restrict__ offs) {
    int i = blockIdx.x * 256 + threadIdx.x;
    if (i <= NN) offs[i] = cnt[i];
}
__global__ void k_permute(const int* __restrict__ src, const int* __restrict__ dst,
                          const float* __restrict__ ea, int* __restrict__ offs,
                          int* __restrict__ ps, int* __restrict__ pd,
                          int* __restrict__ einv, float* __restrict__ eap) {
    int e = blockIdx.x * 256 + threadIdx.x;
    if (e >= EE) return;
    int d = __ldg(dst + e);
    int slot = atomicAdd(&offs[d], 1);
    ps[slot] = __ldg(src + e);
    pd[slot] = d;
    einv[e] = slot;
#pragma unroll
    for (int j = 0; j < 7; j++) eap[(size_t)slot * 7 + j] = __ldg(ea + (size_t)e * 7 + j);
}

// ---------------- init kernels ----------------
__global__ void k_init_vn(const float* __restrict__ emb, float* __restrict__ vn) {
    int i = blockIdx.x * blockDim.x + threadIdx.x;
    if (i < GG * DD) vn[i] = emb[i & (DD - 1)];
}

__global__ void k_init_hin(const int* __restrict__ xn, const float* __restrict__ emb,
                           const float* __restrict__ vne, const float* __restrict__ epsp,
                           float* __restrict__ hin, float* __restrict__ agg) {
    int i = blockIdx.x * blockDim.x + threadIdx.x;
    if (i >= NN * 32) return;
    int row = i >> 5, q = (i & 31) << 2;
    float c = 1.0f + __ldg(epsp);
    float4 a = *(const float4*)(emb + (size_t)xn[row] * DD + q);
    float4 b = *(const float4*)(vne + q);
    a.x += b.x; a.y += b.y; a.z += b.z; a.w += b.w;
    *(float4*)(hin + (size_t)row * DD + q) = a;
    float4 e = make_float4(c * a.x, c * a.y, c * a.z, c * a.w);
    *(float4*)(agg + (size_t)row * DD + q) = e;
}

// ---------------- fused z-encoder (R8 core; writes to dst-sorted slot) ----------------
__global__ __launch_bounds__(256, 2)
void k_zenc(const int* __restrict__ pidx, const float* __restrict__ penc,
            const int* __restrict__ startsg, const float* __restrict__ zinit,
            const float* __restrict__ bn1, const float* __restrict__ zeb,
            const float* __restrict__ bn2, const float* __restrict__ zeWr,
            const int* __restrict__ einv, __half* __restrict__ z2) {
    extern __shared__ unsigned smem[];
    unsigned* As = smem;
    unsigned* Bs = smem + 128 * AS_S;
    __shared__ float sc1[128], sh1[128];

    const int tid = threadIdx.x;
    const int row0 = blockIdx.x * 128;

#pragma unroll
    for (int i = 0; i < 16; i++) {
        int idx = tid + i * 256;
        int r = idx >> 5, c4 = (idx & 31) << 2;
        cp16(Bs + r * BS_S + c4, zeWr + r * 128 + c4);
    }
    cp_commit();

    if (tid < 128) {
        float s = bn1[tid] * rsqrtf(bn1[3 * 128 + tid] + BN_EPS);
        sc1[tid] = s;
        sh1[tid] = bn1[128 + tid] - bn1[2 * 128 + tid] * s;
    }
    __syncthreads();

    const int lane = tid & 31, wid = tid >> 5;
    const int g = lane >> 2, t = lane & 3;
    const int warp_m = wid & 1, warp_n = wid >> 1;
    const int ar = tid >> 1;

    float acc[4][4][4];
#pragma unroll
    for (int mt = 0; mt < 4; mt++)
#pragma unroll
        for (int nt = 0; nt < 4; nt++)
#pragma unroll
            for (int q = 0; q < 4; q++) acc[mt][nt][q] = 0.f;

    const int st = __ldg(startsg + row0 + ar);
    const int en = __ldg(startsg + row0 + ar + 1);

    for (int k0 = 0; k0 < 128; k0 += 64) {
#pragma unroll
        for (int sub = 0; sub < 2; sub++) {
            int cc = (tid & 1) * 32 + sub * 16;
            float4 a[4];
#pragma unroll
            for (int j = 0; j < 4; j++) a[j] = make_float4(0.f, 0.f, 0.f, 0.f);
            for (int p = st; p < en; p++) {
                int zi = __ldg(pidx + p);
                float w = __ldg(penc + p);
                const float* zr = zinit + (size_t)zi * 128 + k0 + cc;
#pragma unroll
                for (int j = 0; j < 4; j++) {
                    float4 v = *(const float4*)(zr + 4 * j);
                    a[j].x += v.x * w; a[j].y += v.y * w; a[j].z += v.z * w; a[j].w += v.w * w;
                }
            }
#pragma unroll
            for (int j = 0; j < 4; j++) {
                int c = cc + 4 * j;
                int gc = k0 + c;
                float y0 = fmaxf(a[j].x * sc1[gc + 0] + sh1[gc + 0], 0.f);
                float y1 = fmaxf(a[j].y * sc1[gc + 1] + sh1[gc + 1], 0.f);
                float y2 = fmaxf(a[j].z * sc1[gc + 2] + sh1[gc + 2], 0.f);
                float y3 = fmaxf(a[j].w * sc1[gc + 3] + sh1[gc + 3], 0.f);
                *(uint4*)(As + ar * AS_S + c) = make_uint4(f2tf(y0), f2tf(y1), f2tf(y2), f2tf(y3));
            }
        }
        if (k0 == 0) cp_wait0();
        __syncthreads();
        MMA_CHUNK(As, Bs + k0 * BS_S, warp_m, warp_n, g, t, acc)
        __syncthreads();
    }

    float sc[8], sh[8];
#pragma unroll
    for (int nt = 0; nt < 4; nt++)
#pragma unroll
        for (int hh = 0; hh < 2; hh++) {
            int c = warp_n * 32 + nt * 8 + 2 * t + hh;
            float s = bn2[c] * rsqrtf(bn2[3 * 128 + c] + BN_EPS);
            sc[nt * 2 + hh] = s;
            sh[nt * 2 + hh] = bn2[128 + c] + (zeb[c] - bn2[2 * 128 + c]) * s;
        }
#pragma unroll
    for (int mt = 0; mt < 4; mt++)
#pragma unroll
        for (int half = 0; half < 2; half++) {
            int gr = row0 + warp_m * 64 + mt * 16 + g + 8 * half;
            size_t slot = (size_t)__ldg(einv + gr);
#pragma unroll
            for (int nt = 0; nt < 4; nt++) {
                float y0 = fmaxf(acc[mt][nt][half * 2 + 0] * sc[nt * 2 + 0] + sh[nt * 2 + 0], 0.f);
                float y1 = fmaxf(acc[mt][nt][half * 2 + 1] * sc[nt * 2 + 1] + sh[nt * 2 + 1], 0.f);
                int cb = warp_n * 32 + nt * 8 + 2 * t;
                *(unsigned*)(z2 + slot * 128 + cb) = pack2h(y0, y1);
            }
        }
}

// ---------------- fused edge GEMM + gather + run-coalesced scatter ----------------
__global__ __launch_bounds__(256, 2)
void k_edge_fused(const __half* __restrict__ z2, const float* __restrict__ Wpr,
                  const float* __restrict__ bp, const float* __restrict__ be,
                  const float* __restrict__ eap, const float* __restrict__ We7,
                  const int* __restrict__ ps, const int* __restrict__ pd,
                  const float* __restrict__ hin, float* __restrict__ agg) {
    extern __shared__ unsigned smem[];
    unsigned* As = smem;
    unsigned* Bs = smem + 128 * AS_S;
    float* eeS = (float*)smem;              // [128][132], aliases As region
    __shared__ float AeS[128 * 8];
    __shared__ float WeS[7 * 128];

    const int tid = threadIdx.x;
    const int row0 = blockIdx.x * 128;

#pragma unroll
    for (int i = 0; i < 16; i++) {
        int idx = tid + i * 256;
        int r = idx >> 5, c4 = (idx & 31) << 2;
        cp16(Bs + r * BS_S + c4, Wpr + r * 128 + c4);
    }
    cp_commit();

    for (int i = tid; i < 128 * 7; i += 256) {
        int r = i / 7, c = i % 7;
        AeS[r * 8 + c] = eap[(size_t)(row0 + r) * 7 + c];
    }
    for (int i = tid; i < 7 * 128; i += 256) WeS[i] = We7[i];

    const int lane = tid & 31, wid = tid >> 5;
    const int g = lane >> 2, t = lane & 3;
    const int warp_m = wid & 1, warp_n = wid >> 1;
    const int arow = tid >> 4, acol = (tid & 15) << 2;

    float acc[4][4][4];
#pragma unroll
    for (int mt = 0; mt < 4; mt++)
#pragma unroll
        for (int nt = 0; nt < 4; nt++)
#pragma unroll
            for (int q = 0; q < 4; q++) acc[mt][nt][q] = 0.f;

    for (int k0 = 0; k0 < 128; k0 += 64) {
        __syncthreads();
#pragma unroll
        for (int p = 0; p < 8; p++) {
            int r = arow + p * 16;
            const __half2* zp = (const __half2*)(z2 + (size_t)(row0 + r) * 128 + k0 + acol);
            float2 f01 = __half22float2(zp[0]);
            float2 f23 = __half22float2(zp[1]);
            unsigned* d = As + r * AS_S + acol;
            d[0] = f2tf(f01.x); d[1] = f2tf(f01.y); d[2] = f2tf(f23.x); d[3] = f2tf(f23.y);
        }
        if (k0 == 0) cp_wait0();
        __syncthreads();
        MMA_CHUNK(As, Bs + k0 * BS_S, warp_m, warp_n, g, t, acc)
    }
    __syncthreads();

    float bsum[8];
#pragma unroll
    for (int nt = 0; nt < 4; nt++)
#pragma unroll
        for (int hh = 0; hh < 2; hh++) {
            int c = warp_n * 32 + nt * 8 + 2 * t + hh;
            bsum[nt * 2 + hh] = bp[c] + be[c];
        }
#pragma unroll
    for (int mt = 0; mt < 4; mt++)
#pragma unroll
        for (int half = 0; half < 2; half++) {
            int lr = warp_m * 64 + mt * 16 + g + 8 * half;
            float a7[7];
#pragma unroll
            for (int k = 0; k < 7; k++) a7[k] = AeS[lr * 8 + k];
#pragma unroll
            for (int nt = 0; nt < 4; nt++) {
                int cb = warp_n * 32 + nt * 8 + 2 * t;
                float y0 = acc[mt][nt][half * 2 + 0] + bsum[nt * 2 + 0];
                float y1 = acc[mt][nt][half * 2 + 1] + bsum[nt * 2 + 1];
#pragma unroll
                for (int k = 0; k < 7; k++) {
                    y0 = fmaf(a7[k], WeS[k * 128 + cb], y0);
                    y1 = fmaf(a7[k], WeS[k * 128 + cb + 1], y1);
                }
                *(float2*)(eeS + lr * 132 + cb) = make_float2(y0, y1);
            }
        }
    __syncthreads();

    // gather + relu + run-coalesced scatter: 16 sorted edges per warp
    {
        float4 accv = make_float4(0.f, 0.f, 0.f, 0.f);
        int dcur = __ldg(pd + row0 + wid * 16);
#pragma unroll 4
        for (int i = 0; i < 16; i++) {
            int lr = wid * 16 + i;
            int e = row0 + lr;
            int s = __ldg(ps + e);
            float4 ev = *(float4*)(eeS + lr * 132 + lane * 4);
            float4 hv = *(const float4*)(hin + (size_t)s * 128 + lane * 4);
            accv.x += fmaxf(hv.x + ev.x, 0.f);
            accv.y += fmaxf(hv.y + ev.y, 0.f);
            accv.z += fmaxf(hv.z + ev.z, 0.f);
            accv.w += fmaxf(hv.w + ev.w, 0.f);
            int dnext = (i < 15) ? __ldg(pd + e + 1) : -1;
            if (dnext != dcur) {
                red_add_v4(agg + (size_t)dcur * 128 + lane * 4, accv);
                accv = make_float4(0.f, 0.f, 0.f, 0.f);
                dcur = dnext;
            }
        }
    }
}

// ---------------- W1 GEMM (R8 verbatim) ----------------
__global__ __launch_bounds__(256, 2)
void tgemm_w1(const float* __restrict__ A, const float* __restrict__ W1r,
              int M, const float* __restrict__ bias, const float* __restrict__ bn,
              float* __restrict__ C) {
    extern __shared__ unsigned smem[];
    unsigned* As = smem;
    unsigned* Bs = smem + 128 * AS_S;
    const int tid = threadIdx.x;
    const int lane = tid & 31, wid = tid >> 5;
    const int g = lane >> 2, t = lane & 3;
    const int warp_m = wid & 1, warp_n = wid >> 1;
    const int row0 = blockIdx.x * 128;
    const int col0 = blockIdx.y * 128;
    const int arow = tid >> 4, acol = (tid & 15) << 2;
    const int Nc = 256;

#pragma unroll
    for (int i = 0; i < 16; i++) {
        int idx = tid + i * 256;
        int r = idx >> 5, c4 = (idx & 31) << 2;
        cp16(Bs + r * BS_S + c4, W1r + (size_t)r * Nc + col0 + c4);
    }
    cp_commit();

    float acc[4][4][4];
#pragma unroll
    for (int mt = 0; mt < 4; mt++)
#pragma unroll
        for (int nt = 0; nt < 4; nt++)
#pragma unroll
            for (int q = 0; q < 4; q++) acc[mt][nt][q] = 0.f;

    for (int k0 = 0; k0 < 128; k0 += 64) {
        __syncthreads();
#pragma unroll
        for (int p = 0; p < 8; p++) {
            int r = arow + p * 16;
            int gr = row0 + r;
            float4 v = make_float4(0.f, 0.f, 0.f, 0.f);
            if (gr < M) v = *(const float4*)(A + (size_t)gr * 128 + k0 + acol);
            *(uint4*)(As + r * AS_S + acol) = make_uint4(f2tf(v.x), f2tf(v.y), f2tf(v.z), f2tf(v.w));
        }
        if (k0 == 0) cp_wait0();
        __syncthreads();
        MMA_CHUNK(As, Bs + k0 * BS_S, warp_m, warp_n, g, t, acc)
    }

    float sc[8], sh[8];
#pragma unroll
    for (int nt = 0; nt < 4; nt++)
#pragma unroll
        for (int hh = 0; hh < 2; hh++) {
            int c = col0 + warp_n * 32 + nt * 8 + 2 * t + hh;
            float s = bn[c] * rsqrtf(bn[3 * Nc + c] + BN_EPS);
            sc[nt * 2 + hh] = s;
            sh[nt * 2 + hh] = bn[Nc + c] + (bias[c] - bn[2 * Nc + c]) * s;
        }
#pragma unroll
    for (int mt = 0; mt < 4; mt++)
#pragma unroll
        for (int half = 0; half < 2; half++) {
            int gr = row0 + warp_m * 64 + mt * 16 + g + 8 * half;
            if (gr >= M) continue;
#pragma unroll
            for (int nt = 0; nt < 4; nt++) {
                float y0 = fmaxf(acc[mt][nt][half * 2 + 0] * sc[nt * 2 + 0] + sh[nt * 2 + 0], 0.f);
                float y1 = fmaxf(acc[mt][nt][half * 2 + 1] * sc[nt * 2 + 1] + sh[nt * 2 + 1], 0.f);
                int cb = warp_n * 32 + nt * 8 + 2 * t;
                *(float2*)(C + (size_t)gr * Nc + col0 + cb) = make_float2(tf32r(y0), tf32r(y1));
            }
        }
}

// ---------------- W2 GEMM (R8 verbatim) ----------------
__global__ __launch_bounds__(256, 2)
void tgemm_w2(const float* __restrict__ A, const float* __restrict__ W2r,
              int M, const float* __restrict__ bias, const float* __restrict__ bn,
              int final_, float* __restrict__ Cf,
              const float* __restrict__ vnext, const int* __restrict__ batch,
              const float* __restrict__ epsp,
              float* __restrict__ hin, float* __restrict__ agg) {
    extern __shared__ unsigned smem[];
    unsigned* As = smem;
    unsigned* Bs = smem + 128 * AS_S;
    const int tid = threadIdx.x;
    const int lane = tid & 31, wid = tid >> 5;
    const int g = lane >> 2, t = lane & 3;
    const int warp_m = wid & 1, warp_n = wid >> 1;
    const int row0 = blockIdx.x * 128;

    float acc[4][4][4];
#pragma unroll
    for (int mt = 0; mt < 4; mt++)
#pragma unroll
        for (int nt = 0; nt < 4; nt++)
#pragma unroll
            for (int q = 0; q < 4; q++) acc[mt][nt][q] = 0.f;

    for (int k0 = 0; k0 < 256; k0 += 64) {
        __syncthreads();
#pragma unroll
        for (int i = 0; i < 8; i++) {
            int idx = tid + i * 256;
            int r = idx >> 4, c4 = (idx & 15) << 2;
            cp16(As + r * AS_S + c4, A + (size_t)(row0 + r) * 256 + k0 + c4);
        }
#pragma unroll
        for (int i = 0; i < 8; i++) {
            int idx = tid + i * 256;
            int r = idx >> 5, c4 = (idx & 31) << 2;
            cp16(Bs + r * BS_S + c4, W2r + (size_t)(k0 + r) * 128 + c4);
        }
        cp_commit();
        cp_wait0();
        __syncthreads();
        MMA_CHUNK(As, Bs, warp_m, warp_n, g, t, acc)
    }

    float sc[8], sh[8];
#pragma unroll
    for (int nt = 0; nt < 4; nt++)
#pragma unroll
        for (int hh = 0; hh < 2; hh++) {
            int c = warp_n * 32 + nt * 8 + 2 * t + hh;
            float s = bn[c] * rsqrtf(bn[3 * 128 + c] + BN_EPS);
            sc[nt * 2 + hh] = s;
            sh[nt * 2 + hh] = bn[128 + c] + (bias[c] - bn[2 * 128 + c]) * s;
        }

    float ceps = final_ ? 0.f : (1.0f + __ldg(epsp));
#pragma unroll
    for (int mt = 0; mt < 4; mt++)
#pragma unroll
        for (int half = 0; half < 2; half++) {
            int gr = row0 + warp_m * 64 + mt * 16 + g + 8 * half;
            if (gr >= M) continue;
            if (final_) {
#pragma unroll
                for (int nt = 0; nt < 4; nt++) {
                    float y0 = acc[mt][nt][half * 2 + 0] * sc[nt * 2 + 0] + sh[nt * 2 + 0];
                    float y1 = acc[mt][nt][half * 2 + 1] * sc[nt * 2 + 1] + sh[nt * 2 + 1];
                    int cb = warp_n * 32 + nt * 8 + 2 * t;
                    *(float2*)(Cf + (size_t)gr * 128 + cb) = make_float2(y0, y1);
                }
            } else {
                int b = __ldg(batch + gr);
                const float* vrow = vnext + (size_t)b * 128;
#pragma unroll
                for (int nt = 0; nt < 4; nt++) {
                    int cb = warp_n * 32 + nt * 8 + 2 * t;
                    float y0 = fmaxf(acc[mt][nt][half * 2 + 0] * sc[nt * 2 + 0] + sh[nt * 2 + 0], 0.f);
                    float y1 = fmaxf(acc[mt][nt][half * 2 + 1] * sc[nt * 2 + 1] + sh[nt * 2 + 1], 0.f);
                    float h0 = y0 + __ldg(vrow + cb);
                    float h1 = y1 + __ldg(vrow + cb + 1);
                    *(float2*)(hin + (size_t)gr * 128 + cb) = make_float2(h0, h1);
                    *(float2*)(agg + (size_t)gr * 128 + cb) = make_float2(ceps * h0, ceps * h1);
                }
            }
        }
}

// ---------------- virtual node ----------------
__global__ void k_vn_agg(const float* __restrict__ hin, const int* __restrict__ batch,
                         const float* __restrict__ vn, float* __restrict__ vt) {
    int g = blockIdx.x, c = threadIdx.x;
    int lo = 0, hi = NN;
    while (lo < hi) { int m = (lo + hi) >> 1; if (batch[m] < g) lo = m + 1; else hi = m; }
    int start = lo;
    lo = start; hi = NN;
    while (lo < hi) { int m = (lo + hi) >> 1; if (batch[m] < g + 1) lo = m + 1; else hi = m; }
    int end = lo;
    float sum = 0.f;
    for (int i = start; i < end; i++) sum += hin[(size_t)i * DD + c];
    vt[g * DD + c] = sum + vn[g * DD + c];
}

__global__ void k_vn_mlp(const float* __restrict__ vt,
                         const float* __restrict__ W1, const float* __restrict__ b1,
                         const float* __restrict__ bn1,
                         const float* __restrict__ W2, const float* __restrict__ b2,
                         const float* __restrict__ bn2, float* __restrict__ vn) {
    __shared__ float xr[DD];
    __shared__ float tr[2 * DD];
    int g = blockIdx.x, tid = threadIdx.x;
    if (tid < DD) xr[tid] = vt[g * DD + tid];
    __syncthreads();
    float acc = b1[tid];
#pragma unroll 8
    for (int k = 0; k < DD; k++) acc = fmaf(xr[k], W1[(size_t)k * 2 * DD + tid], acc);
    float s = bn1[tid] * rsqrtf(bn1[3 * 2 * DD + tid] + BN_EPS);
    acc = (acc - bn1[2 * 2 * DD + tid]) * s + bn1[2 * DD + tid];
    tr[tid] = fmaxf(acc, 0.f);
    __syncthreads();
    if (tid < DD) {
        float a2 = b2[tid];
#pragma unroll 8
        for (int k = 0; k < 2 * DD; k++) a2 = fmaf(tr[k], W2[(size_t)k * DD + tid], a2);
        float s2 = bn2[tid] * rsqrtf(bn2[3 * DD + tid] + BN_EPS);
        a2 = (a2 - bn2[2 * DD + tid]) * s2 + bn2[DD + tid];
        vn[g * DD + tid] = fmaxf(a2, 0.f);
    }
}

// ---------------- host launcher ----------------
extern "C" void kernel_launch(void* const* d_in, const int* in_sizes, int n_in,
                              void* d_out, int out_size) {
    const int*   x_node     = (const int*)d_in[0];
    const int*   edge_index = (const int*)d_in[1];
    const float* edge_attr  = (const float*)d_in[2];
    const int*   batch      = (const int*)d_in[3];
    const int*   pos_index  = (const int*)d_in[4];
    const float* pos_enc    = (const float*)d_in[5];
    const int*   pos_batch  = (const int*)d_in[6];
    const float* node_emb   = (const float*)d_in[7];
    const float* z_init     = (const float*)d_in[8];
    const float* ze_bn1     = (const float*)d_in[9];
    const float* ze_W       = (const float*)d_in[10];
    const float* ze_b       = (const float*)d_in[11];
    const float* ze_bn2     = (const float*)d_in[12];
    const float* vn_emb     = (const float*)d_in[13];
    const float* conv_We    = (const float*)d_in[14];
    const float* conv_be    = (const float*)d_in[15];
    const float* conv_Wp    = (const float*)d_in[16];
    const float* conv_bp    = (const float*)d_in[17];
    const float* conv_W1    = (const float*)d_in[18];
    const float* conv_b1    = (const float*)d_in[19];
    const float* conv_bn    = (const float*)d_in[20];
    const float* conv_W2    = (const float*)d_in[21];
    const float* conv_b2    = (const float*)d_in[22];
    const float* conv_eps   = (const float*)d_in[23];
    const float* layer_bn   = (const float*)d_in[24];
    const float* vn_W1      = (const float*)d_in[25];
    const float* vn_b1      = (const float*)d_in[26];
    const float* vn_bn1     = (const float*)d_in[27];
    const float* vn_W2      = (const float*)d_in[28];
    const float* vn_b2      = (const float*)d_in[29];
    const float* vn_bn2     = (const float*)d_in[30];

    __half* z2;
    float *hin, *agg, *t2, *vn, *vt, *wh, *eap;
    int *sts, *cnt, *offs, *ps, *pd, *einv;
    cudaGetSymbolAddress((void**)&z2,   g_z2);
    cudaGetSymbolAddress((void**)&hin,  g_hin);
    cudaGetSymbolAddress((void**)&agg,  g_agg);
    cudaGetSymbolAddress((void**)&t2,   g_t2);
    cudaGetSymbolAddress((void**)&vn,   g_vn);
    cudaGetSymbolAddress((void**)&vt,   g_vt);
    cudaGetSymbolAddress((void**)&wh,   g_wh);
    cudaGetSymbolAddress((void**)&sts,  g_st);
    cudaGetSymbolAddress((void**)&cnt,  g_cnt);
    cudaGetSymbolAddress((void**)&offs, g_offs);
    cudaGetSymbolAddress((void**)&ps,   g_ps);
    cudaGetSymbolAddress((void**)&pd,   g_pd);
    cudaGetSymbolAddress((void**)&einv, g_einv);
    cudaGetSymbolAddress((void**)&eap,  g_eap);

    cudaFuncSetAttribute(k_zenc, cudaFuncAttributeMaxDynamicSharedMemorySize, SM_BIG);
    cudaFuncSetAttribute(k_edge_fused, cudaFuncAttributeMaxDynamicSharedMemorySize, SM_BIG);
    cudaFuncSetAttribute(tgemm_w1, cudaFuncAttributeMaxDynamicSharedMemorySize, SM_BIG);
    cudaFuncSetAttribute(tgemm_w2, cudaFuncAttributeMaxDynamicSharedMemorySize, SM_W2);

    float* h = (float*)d_out;
    const int* srcp = edge_index;
    const int* dstp = edge_index + EE;

    // independent prep
    k_prep<<<1024, 256>>>(ze_W, conv_Wp, conv_W1, conv_W2, wh);
    k_starts<<<(PP + 256) / 256, 256>>>(pos_batch, sts);
    k_init_vn<<<(GG * DD + 255) / 256, 256>>>(vn_emb, vn);
    k_init_hin<<<(NN * 32 + 255) / 256, 256>>>(x_node, node_emb, vn_emb, conv_eps, hin, agg);

    // counting sort by dst (per call; graph-capturable)
    k_zero_cnt<<<(NN + 2 + 255) / 256, 256>>>(cnt);
    k_hist<<<(EE + 255) / 256, 256>>>(dstp, cnt);
    k_scan<<<1, 1024>>>(cnt);
    k_copy_offs<<<(NN + 1 + 255) / 256, 256>>>(cnt, offs);
    k_permute<<<(EE + 255) / 256, 256>>>(srcp, dstp, edge_attr, offs, ps, pd, einv, eap);

    // z encoder writes into dst-sorted slots
    k_zenc<<<EE / 128, 256, SM_BIG>>>(pos_index, pos_enc, sts, z_init,
                                      ze_bn1, ze_b, ze_bn2, wh + OFF_ZEW, einv, z2);

    const int nblk = (NN + 127) / 128;

    for (int l = 0; l < LL; l++) {
        k_edge_fused<<<EE / 128, 256, SM_BIG>>>(z2, wh + OFF_WP(l),
                                                conv_bp + l * DD, conv_be + l * DD,
                                                eap, conv_We + (size_t)l * 7 * DD,
                                                ps, pd, hin, agg);
        if (l < LL - 1) {
            k_vn_agg<<<GG, DD>>>(hin, batch, vn, vt);
            k_vn_mlp<<<GG, 256>>>(vt, vn_W1 + (size_t)l * DD * 2 * DD, vn_b1 + l * 2 * DD,
                                  vn_bn1 + (size_t)l * 4 * 2 * DD,
                                  vn_W2 + (size_t)l * 2 * DD * DD, vn_b2 + l * DD,
                                  vn_bn2 + (size_t)l * 4 * DD, vn);
        }
        tgemm_w1<<<dim3(nblk, 2), 256, SM_BIG>>>(agg, wh + OFF_W1(l),
                                                 NN, conv_b1 + l * 2 * DD,
                                                 conv_bn + (size_t)l * 4 * 2 * DD, t2);
        int fin = (l == LL - 1) ? 1 : 0;
        tgemm_w2<<<dim3(nblk, 1), 256, SM_W2>>>(t2, wh + OFF_W2(l),
                                                NN, conv_b2 + l * DD,
                                                layer_bn + (size_t)l * 4 * DD,
                                                fin, h, vn, batch,
                                                conv_eps + (fin ? l : l + 1),
                                                hin, agg);
    }
}

// round 12
// speedup vs baseline: 1.2538x; 1.2480x over previous
#include <cuda_runtime.h>
#include <cuda_fp16.h>
#include <cstddef>
#include <cstdint>

#define NN 100000
#define EE 640000
#define PP 640000
#define DD 128
#define GG 128
#define LL 3
#define BN_EPS 1e-5f

// ---------------- device scratch ----------------
__device__ __half g_z2 [(size_t)EE * DD];            // fp16 z after encoder
__device__ float  g_hin[(size_t)NN * DD];            // fp32
__device__ float  g_agg[(size_t)NN * DD];            // fp32 (atomic target)
__device__ float  g_t2 [((size_t)NN + 128) * 2 * DD];// tf32-rounded fp32 (+pad)
__device__ float  g_vn [GG * DD];
__device__ float  g_vt [GG * DD];
__device__ float  g_wh [262144];                     // tf32-rounded weights
__device__ __half g_wph[49152];                      // fp16 n-major Wp (3 layers)
__device__ int    g_st [EE + 1];                     // pos_batch segment starts

#define OFF_ZEW 0
#define OFF_WP(l) (16384 + (l) * 81920)
#define OFF_W1(l) (16384 + (l) * 81920 + 16384)
#define OFF_W2(l) (16384 + (l) * 81920 + 49152)

// ---------------- helpers ----------------
__device__ __forceinline__ void red_add_v4(float* p, float4 v) {
    asm volatile("red.global.add.v4.f32 [%0], {%1,%2,%3,%4};"
                 :: "l"(p), "f"(v.x), "f"(v.y), "f"(v.z), "f"(v.w) : "memory");
}
__device__ __forceinline__ unsigned f2tf(float f) {
    unsigned u;
    asm("cvt.rna.tf32.f32 %0, %1;" : "=r"(u) : "f"(f));
    return u;
}
__device__ __forceinline__ float tf32r(float f) { return __uint_as_float(f2tf(f)); }
__device__ __forceinline__ void mma_tf32(float* c, const unsigned* a, const unsigned* b) {
    asm volatile("mma.sync.aligned.m16n8k8.row.col.f32.tf32.tf32.f32 "
                 "{%0,%1,%2,%3}, {%4,%5,%6,%7}, {%8,%9}, {%0,%1,%2,%3};"
                 : "+f"(c[0]), "+f"(c[1]), "+f"(c[2]), "+f"(c[3])
                 : "r"(a[0]), "r"(a[1]), "r"(a[2]), "r"(a[3]),
                   "r"(b[0]), "r"(b[1]));
}
__device__ __forceinline__ void mma_f16(float* c, const unsigned* a, const unsigned* b) {
    asm volatile("mma.sync.aligned.m16n8k16.row.col.f32.f16.f16.f32 "
                 "{%0,%1,%2,%3},{%4,%5,%6,%7},{%8,%9},{%0,%1,%2,%3};"
                 : "+f"(c[0]), "+f"(c[1]), "+f"(c[2]), "+f"(c[3])
                 : "r"(a[0]), "r"(a[1]), "r"(a[2]), "r"(a[3]), "r"(b[0]), "r"(b[1]));
}
__device__ __forceinline__ unsigned pack2h(float x, float y) {
    __half2 h = __floats2half2_rn(x, y);
    return *(unsigned*)&h;
}
__device__ __forceinline__ void cp16(void* s, const void* g) {
    unsigned sa = (unsigned)__cvta_generic_to_shared(s);
    asm volatile("cp.async.cg.shared.global [%0], [%1], 16;" :: "r"(sa), "l"(g));
}
__device__ __forceinline__ void cp_commit() {
    asm volatile("cp.async.commit_group;" ::: "memory");
}
__device__ __forceinline__ void cp_wait0() {
    asm volatile("cp.async.wait_group 0;" ::: "memory");
}

#define AS_S 68
#define BS_S 132
#define SM_BIG ((128 * AS_S + 128 * BS_S) * 4)   // 102400 B (zenc / W1)
#define SM_W2  ((128 * AS_S + 64 * BS_S) * 4)    // 68608 B
#define SH2 136                                  // halves per row, fp16 tiles
#define SM_EDGE (2 * 128 * SH2 * 2)              // 69632 B : As + Bs fp16

#define MMA_CHUNK(As, Bs, warp_m, warp_n, g, t, acc)                               \
    _Pragma("unroll")                                                              \
    for (int kk = 0; kk < 64; kk += 8) {                                           \
        unsigned af[4][4], bf[4][2];                                               \
        _Pragma("unroll")                                                          \
        for (int mt = 0; mt < 4; mt++) {                                           \
            int mb = (warp_m) * 64 + mt * 16;                                      \
            af[mt][0] = (As)[(mb + (g)) * AS_S + kk + (t)];                        \
            af[mt][1] = (As)[(mb + (g) + 8) * AS_S + kk + (t)];                    \
            af[mt][2] = (As)[(mb + (g)) * AS_S + kk + (t) + 4];                    \
            af[mt][3] = (As)[(mb + (g) + 8) * AS_S + kk + (t) + 4];                \
        }                                                                          \
        _Pragma("unroll")                                                          \
        for (int nt = 0; nt < 4; nt++) {                                           \
            int n = (warp_n) * 32 + nt * 8 + (g);                                  \
            bf[nt][0] = (Bs)[(kk + (t)) * BS_S + n];                               \
            bf[nt][1] = (Bs)[(kk + (t) + 4) * BS_S + n];                           \
        }                                                                          \
        _Pragma("unroll")                                                          \
        for (int mt = 0; mt < 4; mt++)                                             \
            _Pragma("unroll")                                                      \
            for (int nt = 0; nt < 4; nt++)                                         \
                mma_tf32(acc[mt][nt], af[mt], bf[nt]);                             \
    }

// ---------------- prep kernels ----------------
__global__ void k_prep(const float* __restrict__ zeW, const float* __restrict__ Wp,
                       const float* __restrict__ W1, const float* __restrict__ W2,
                       float* __restrict__ wh) {
    int i = blockIdx.x * 256 + threadIdx.x;
    if (i >= 262144) return;
    if (i < 16384) { wh[OFF_ZEW + i] = tf32r(zeW[i]); return; }
    int j = i - 16384;
    int l = j / 81920;
    j = j % 81920;
    if (j < 16384)       wh[OFF_WP(l) + j]           = tf32r(Wp[(size_t)l * 16384 + j]);
    else if (j < 49152)  wh[OFF_W1(l) + (j - 16384)] = tf32r(W1[(size_t)l * 32768 + j - 16384]);
    else                 wh[OFF_W2(l) + (j - 49152)] = tf32r(W2[(size_t)l * 32768 + j - 49152]);
}

// fp16 n-major Wp for fp16 MMA: wph[l][n][k] = Wp[l][k][n]
__global__ void k_prep16(const float* __restrict__ Wp, __half* __restrict__ wph) {
    int i = blockIdx.x * 256 + threadIdx.x;
    if (i >= 49152) return;
    int l = i / 16384;
    int j = i % 16384;
    int n = j >> 7, k = j & 127;
    wph[i] = __float2half(Wp[(size_t)l * 16384 + k * 128 + n]);
}

__global__ void k_starts(const int* __restrict__ pbatch, int* __restrict__ starts) {
    int p = blockIdx.x * 256 + threadIdx.x;
    if (p > PP) return;
    int prev = (p == 0) ? -1 : __ldg(pbatch + p - 1);
    int cur  = (p == PP) ? EE : __ldg(pbatch + p);
    for (int seg = prev + 1; seg <= cur; seg++) starts[seg] = p;
}

// ---------------- init kernels ----------------
__global__ void k_init_vn(const float* __restrict__ emb, float* __restrict__ vn) {
    int i = blockIdx.x * blockDim.x + threadIdx.x;
    if (i < GG * DD) vn[i] = emb[i & (DD - 1)];
}

__global__ void k_init_hin(const int* __restrict__ xn, const float* __restrict__ emb,
                           const float* __restrict__ vne, const float* __restrict__ epsp,
                           float* __restrict__ hin, float* __restrict__ agg) {
    int i = blockIdx.x * blockDim.x + threadIdx.x;
    if (i >= NN * 32) return;
    int row = i >> 5, q = (i & 31) << 2;
    float c = 1.0f + __ldg(epsp);
    float4 a = *(const float4*)(emb + (size_t)xn[row] * DD + q);
    float4 b = *(const float4*)(vne + q);
    a.x += b.x; a.y += b.y; a.z += b.z; a.w += b.w;
    *(float4*)(hin + (size_t)row * DD + q) = a;
    float4 e = make_float4(c * a.x, c * a.y, c * a.z, c * a.w);
    *(float4*)(agg + (size_t)row * DD + q) = e;
}

// ---------------- fused z-encoder (R8 verbatim) ----------------
__global__ __launch_bounds__(256, 2)
void k_zenc(const int* __restrict__ pidx, const float* __restrict__ penc,
            const int* __restrict__ startsg, const float* __restrict__ zinit,
            const float* __restrict__ bn1, const float* __restrict__ zeb,
            const float* __restrict__ bn2, const float* __restrict__ zeWr,
            __half* __restrict__ z2) {
    extern __shared__ unsigned smem[];
    unsigned* As = smem;
    unsigned* Bs = smem + 128 * AS_S;
    __shared__ float sc1[128], sh1[128];

    const int tid = threadIdx.x;
    const int row0 = blockIdx.x * 128;

#pragma unroll
    for (int i = 0; i < 16; i++) {
        int idx = tid + i * 256;
        int r = idx >> 5, c4 = (idx & 31) << 2;
        cp16(Bs + r * BS_S + c4, zeWr + r * 128 + c4);
    }
    cp_commit();

    if (tid < 128) {
        float s = bn1[tid] * rsqrtf(bn1[3 * 128 + tid] + BN_EPS);
        sc1[tid] = s;
        sh1[tid] = bn1[128 + tid] - bn1[2 * 128 + tid] * s;
    }
    __syncthreads();

    const int lane = tid & 31, wid = tid >> 5;
    const int g = lane >> 2, t = lane & 3;
    const int warp_m = wid & 1, warp_n = wid >> 1;
    const int ar = tid >> 1;

    float acc[4][4][4];
#pragma unroll
    for (int mt = 0; mt < 4; mt++)
#pragma unroll
        for (int nt = 0; nt < 4; nt++)
#pragma unroll
            for (int q = 0; q < 4; q++) acc[mt][nt][q] = 0.f;

    const int st = __ldg(startsg + row0 + ar);
    const int en = __ldg(startsg + row0 + ar + 1);

    for (int k0 = 0; k0 < 128; k0 += 64) {
#pragma unroll
        for (int sub = 0; sub < 2; sub++) {
            int cc = (tid & 1) * 32 + sub * 16;
            float4 a[4];
#pragma unroll
            for (int j = 0; j < 4; j++) a[j] = make_float4(0.f, 0.f, 0.f, 0.f);
            for (int p = st; p < en; p++) {
                int zi = __ldg(pidx + p);
                float w = __ldg(penc + p);
                const float* zr = zinit + (size_t)zi * 128 + k0 + cc;
#pragma unroll
                for (int j = 0; j < 4; j++) {
                    float4 v = *(const float4*)(zr + 4 * j);
                    a[j].x += v.x * w; a[j].y += v.y * w; a[j].z += v.z * w; a[j].w += v.w * w;
                }
            }
#pragma unroll
            for (int j = 0; j < 4; j++) {
                int c = cc + 4 * j;
                int gc = k0 + c;
                float y0 = fmaxf(a[j].x * sc1[gc + 0] + sh1[gc + 0], 0.f);
                float y1 = fmaxf(a[j].y * sc1[gc + 1] + sh1[gc + 1], 0.f);
                float y2 = fmaxf(a[j].z * sc1[gc + 2] + sh1[gc + 2], 0.f);
                float y3 = fmaxf(a[j].w * sc1[gc + 3] + sh1[gc + 3], 0.f);
                *(uint4*)(As + ar * AS_S + c) = make_uint4(f2tf(y0), f2tf(y1), f2tf(y2), f2tf(y3));
            }
        }
        if (k0 == 0) cp_wait0();
        __syncthreads();
        MMA_CHUNK(As, Bs + k0 * BS_S, warp_m, warp_n, g, t, acc)
        __syncthreads();
    }

    float sc[8], sh[8];
#pragma unroll
    for (int nt = 0; nt < 4; nt++)
#pragma unroll
        for (int hh = 0; hh < 2; hh++) {
            int c = warp_n * 32 + nt * 8 + 2 * t + hh;
            float s = bn2[c] * rsqrtf(bn2[3 * 128 + c] + BN_EPS);
            sc[nt * 2 + hh] = s;
            sh[nt * 2 + hh] = bn2[128 + c] + (zeb[c] - bn2[2 * 128 + c]) * s;
        }
#pragma unroll
    for (int mt = 0; mt < 4; mt++)
#pragma unroll
        for (int half = 0; half < 2; half++) {
            int gr = row0 + warp_m * 64 + mt * 16 + g + 8 * half;
#pragma unroll
            for (int nt = 0; nt < 4; nt++) {
                float y0 = fmaxf(acc[mt][nt][half * 2 + 0] * sc[nt * 2 + 0] + sh[nt * 2 + 0], 0.f);
                float y1 = fmaxf(acc[mt][nt][half * 2 + 1] * sc[nt * 2 + 1] + sh[nt * 2 + 1], 0.f);
                int cb = warp_n * 32 + nt * 8 + 2 * t;
                *(unsigned*)(z2 + (size_t)gr * 128 + cb) = pack2h(y0, y1);
            }
        }
}

// ---------------- fused edge GEMM (fp16 MMA) + gather + scatter ----------------
// A = z2 (fp16, direct cp.async), B = Wp fp16 n-major. K=128 in one pass.
__global__ __launch_bounds__(256, 2)
void k_edge_fused(const __half* __restrict__ z2, const __half* __restrict__ Wph,
                  const float* __restrict__ bp, const float* __restrict__ be,
                  const float* __restrict__ Ae, const float* __restrict__ We7,
                  const int* __restrict__ src, const int* __restrict__ dst,
                  const float* __restrict__ hin, float* __restrict__ agg) {
    extern __shared__ __half hsm[];
    __half* As = hsm;                    // [128][SH2]
    __half* Bs = hsm + 128 * SH2;        // [128][SH2] n-major
    float* eeS = (float*)hsm;            // [128][132] floats, aliases As/Bs
    __shared__ float AeS[128 * 8];
    __shared__ float WeS[7 * 128];

    const int tid = threadIdx.x;
    const int row0 = blockIdx.x * 128;

    // A (z2 rows, fp16) + B (Wp n-major, fp16) via cp.async — no conversion
#pragma unroll
    for (int i = 0; i < 8; i++) {
        int idx = tid + i * 256;
        int r = idx >> 4, c8 = (idx & 15) << 3;    // 8 halves per 16B
        cp16(As + r * SH2 + c8, z2 + (size_t)(row0 + r) * 128 + c8);
        cp16(Bs + r * SH2 + c8, Wph + r * 128 + c8);
    }
    cp_commit();

    for (int i = tid; i < 128 * 7; i += 256) {
        int r = i / 7, c = i % 7;
        AeS[r * 8 + c] = Ae[(size_t)(row0 + r) * 7 + c];
    }
    for (int i = tid; i < 7 * 128; i += 256) WeS[i] = We7[i];

    const int lane = tid & 31, wid = tid >> 5;
    const int g = lane >> 2, t = lane & 3;
    const int warp_m = wid & 1, warp_n = wid >> 1;

    float acc[4][4][4];
#pragma unroll
    for (int mt = 0; mt < 4; mt++)
#pragma unroll
        for (int nt = 0; nt < 4; nt++)
#pragma unroll
            for (int q = 0; q < 4; q++) acc[mt][nt][q] = 0.f;

    cp_wait0();
    __syncthreads();

#pragma unroll
    for (int kk = 0; kk < 128; kk += 16) {
        unsigned af[4][4], bf[4][2];
#pragma unroll
        for (int mt = 0; mt < 4; mt++) {
            const __half* pa = As + (warp_m * 64 + mt * 16 + g) * SH2 + kk + 2 * t;
            af[mt][0] = *(const unsigned*)pa;
            af[mt][1] = *(const unsigned*)(pa + 8 * SH2);
            af[mt][2] = *(const unsigned*)(pa + 8);
            af[mt][3] = *(const unsigned*)(pa + 8 * SH2 + 8);
        }
#pragma unroll
        for (int nt = 0; nt < 4; nt++) {
            const __half* pb = Bs + (warp_n * 32 + nt * 8 + g) * SH2 + kk + 2 * t;
            bf[nt][0] = *(const unsigned*)pb;
            bf[nt][1] = *(const unsigned*)(pb + 8);
        }
#pragma unroll
        for (int mt = 0; mt < 4; mt++)
#pragma unroll
            for (int nt = 0; nt < 4; nt++)
                mma_f16(acc[mt][nt], af[mt], bf[nt]);
    }
    __syncthreads();   // all warps done reading As/Bs before aliasing as eeS

    float bsum[8];
#pragma unroll
    for (int nt = 0; nt < 4; nt++)
#pragma unroll
        for (int hh = 0; hh < 2; hh++) {
            int c = warp_n * 32 + nt * 8 + 2 * t + hh;
            bsum[nt * 2 + hh] = bp[c] + be[c];
        }
#pragma unroll
    for (int mt = 0; mt < 4; mt++)
#pragma unroll
        for (int half = 0; half < 2; half++) {
            int lr = warp_m * 64 + mt * 16 + g + 8 * half;
            float a7[7];
#pragma unroll
            for (int k = 0; k < 7; k++) a7[k] = AeS[lr * 8 + k];
#pragma unroll
            for (int nt = 0; nt < 4; nt++) {
                int cb = warp_n * 32 + nt * 8 + 2 * t;
                float y0 = acc[mt][nt][half * 2 + 0] + bsum[nt * 2 + 0];
                float y1 = acc[mt][nt][half * 2 + 1] + bsum[nt * 2 + 1];
#pragma unroll
                for (int k = 0; k < 7; k++) {
                    y0 = fmaf(a7[k], WeS[k * 128 + cb], y0);
                    y1 = fmaf(a7[k], WeS[k * 128 + cb + 1], y1);
                }
                *(float2*)(eeS + lr * 132 + cb) = make_float2(y0, y1);
            }
        }
    __syncthreads();

    // gather + relu + scatter: warp per edge
#pragma unroll 4
    for (int i = 0; i < 16; i++) {
        int lr = wid * 16 + i;
        int e = row0 + lr;
        int s = __ldg(src + e), d = __ldg(dst + e);
        float4 ev = *(float4*)(eeS + lr * 132 + lane * 4);
        float4 hv = *(const float4*)(hin + (size_t)s * 128 + lane * 4);
        float4 m;
        m.x = fmaxf(hv.x + ev.x, 0.f);
        m.y = fmaxf(hv.y + ev.y, 0.f);
        m.z = fmaxf(hv.z + ev.z, 0.f);
        m.w = fmaxf(hv.w + ev.w, 0.f);
        red_add_v4(agg + (size_t)d * 128 + lane * 4, m);
    }
}

// ---------------- W1 GEMM (R8 verbatim) ----------------
__global__ __launch_bounds__(256, 2)
void tgemm_w1(const float* __restrict__ A, const float* __restrict__ W1r,
              int M, const float* __restrict__ bias, const float* __restrict__ bn,
              float* __restrict__ C) {
    extern __shared__ unsigned smem[];
    unsigned* As = smem;
    unsigned* Bs = smem + 128 * AS_S;
    const int tid = threadIdx.x;
    const int lane = tid & 31, wid = tid >> 5;
    const int g = lane >> 2, t = lane & 3;
    const int warp_m = wid & 1, warp_n = wid >> 1;
    const int row0 = blockIdx.x * 128;
    const int col0 = blockIdx.y * 128;
    const int arow = tid >> 4, acol = (tid & 15) << 2;
    const int Nc = 256;

#pragma unroll
    for (int i = 0; i < 16; i++) {
        int idx = tid + i * 256;
        int r = idx >> 5, c4 = (idx & 31) << 2;
        cp16(Bs + r * BS_S + c4, W1r + (size_t)r * Nc + col0 + c4);
    }
    cp_commit();

    float acc[4][4][4];
#pragma unroll
    for (int mt = 0; mt < 4; mt++)
#pragma unroll
        for (int nt = 0; nt < 4; nt++)
#pragma unroll
            for (int q = 0; q < 4; q++) acc[mt][nt][q] = 0.f;

    for (int k0 = 0; k0 < 128; k0 += 64) {
        __syncthreads();
#pragma unroll
        for (int p = 0; p < 8; p++) {
            int r = arow + p * 16;
            int gr = row0 + r;
            float4 v = make_float4(0.f, 0.f, 0.f, 0.f);
            if (gr < M) v = *(const float4*)(A + (size_t)gr * 128 + k0 + acol);
            *(uint4*)(As + r * AS_S + acol) = make_uint4(f2tf(v.x), f2tf(v.y), f2tf(v.z), f2tf(v.w));
        }
        if (k0 == 0) cp_wait0();
        __syncthreads();
        MMA_CHUNK(As, Bs + k0 * BS_S, warp_m, warp_n, g, t, acc)
    }

    float sc[8], sh[8];
#pragma unroll
    for (int nt = 0; nt < 4; nt++)
#pragma unroll
        for (int hh = 0; hh < 2; hh++) {
            int c = col0 + warp_n * 32 + nt * 8 + 2 * t + hh;
            float s = bn[c] * rsqrtf(bn[3 * Nc + c] + BN_EPS);
            sc[nt * 2 + hh] = s;
            sh[nt * 2 + hh] = bn[Nc + c] + (bias[c] - bn[2 * Nc + c]) * s;
        }
#pragma unroll
    for (int mt = 0; mt < 4; mt++)
#pragma unroll
        for (int half = 0; half < 2; half++) {
            int gr = row0 + warp_m * 64 + mt * 16 + g + 8 * half;
            if (gr >= M) continue;
#pragma unroll
            for (int nt = 0; nt < 4; nt++) {
                float y0 = fmaxf(acc[mt][nt][half * 2 + 0] * sc[nt * 2 + 0] + sh[nt * 2 + 0], 0.f);
                float y1 = fmaxf(acc[mt][nt][half * 2 + 1] * sc[nt * 2 + 1] + sh[nt * 2 + 1], 0.f);
                int cb = warp_n * 32 + nt * 8 + 2 * t;
                *(float2*)(C + (size_t)gr * Nc + col0 + cb) = make_float2(tf32r(y0), tf32r(y1));
            }
        }
}

// ---------------- W2 GEMM (R8 verbatim) ----------------
__global__ __launch_bounds__(256, 2)
void tgemm_w2(const float* __restrict__ A, const float* __restrict__ W2r,
              int M, const float* __restrict__ bias, const float* __restrict__ bn,
              int final_, float* __restrict__ Cf,
              const float* __restrict__ vnext, const int* __restrict__ batch,
              const float* __restrict__ epsp,
              float* __restrict__ hin, float* __restrict__ agg) {
    extern __shared__ unsigned smem[];
    unsigned* As = smem;
    unsigned* Bs = smem + 128 * AS_S;
    const int tid = threadIdx.x;
    const int lane = tid & 31, wid = tid >> 5;
    const int g = lane >> 2, t = lane & 3;
    const int warp_m = wid & 1, warp_n = wid >> 1;
    const int row0 = blockIdx.x * 128;

    float acc[4][4][4];
#pragma unroll
    for (int mt = 0; mt < 4; mt++)
#pragma unroll
        for (int nt = 0; nt < 4; nt++)
#pragma unroll
            for (int q = 0; q < 4; q++) acc[mt][nt][q] = 0.f;

    for (int k0 = 0; k0 < 256; k0 += 64) {
        __syncthreads();
#pragma unroll
        for (int i = 0; i < 8; i++) {
            int idx = tid + i * 256;
            int r = idx >> 4, c4 = (idx & 15) << 2;
            cp16(As + r * AS_S + c4, A + (size_t)(row0 + r) * 256 + k0 + c4);
        }
#pragma unroll
        for (int i = 0; i < 8; i++) {
            int idx = tid + i * 256;
            int r = idx >> 5, c4 = (idx & 31) << 2;
            cp16(Bs + r * BS_S + c4, W2r + (size_t)(k0 + r) * 128 + c4);
        }
        cp_commit();
        cp_wait0();
        __syncthreads();
        MMA_CHUNK(As, Bs, warp_m, warp_n, g, t, acc)
    }

    float sc[8], sh[8];
#pragma unroll
    for (int nt = 0; nt < 4; nt++)
#pragma unroll
        for (int hh = 0; hh < 2; hh++) {
            int c = warp_n * 32 + nt * 8 + 2 * t + hh;
            float s = bn[c] * rsqrtf(bn[3 * 128 + c] + BN_EPS);
            sc[nt * 2 + hh] = s;
            sh[nt * 2 + hh] = bn[128 + c] + (bias[c] - bn[2 * 128 + c]) * s;
        }

    float ceps = final_ ? 0.f : (1.0f + __ldg(epsp));
#pragma unroll
    for (int mt = 0; mt < 4; mt++)
#pragma unroll
        for (int half = 0; half < 2; half++) {
            int gr = row0 + warp_m * 64 + mt * 16 + g + 8 * half;
            if (gr >= M) continue;
            if (final_) {
#pragma unroll
                for (int nt = 0; nt < 4; nt++) {
                    float y0 = acc[mt][nt][half * 2 + 0] * sc[nt * 2 + 0] + sh[nt * 2 + 0];
                    float y1 = acc[mt][nt][half * 2 + 1] * sc[nt * 2 + 1] + sh[nt * 2 + 1];
                    int cb = warp_n * 32 + nt * 8 + 2 * t;
                    *(float2*)(Cf + (size_t)gr * 128 + cb) = make_float2(y0, y1);
                }
            } else {
                int b = __ldg(batch + gr);
                const float* vrow = vnext + (size_t)b * 128;
#pragma unroll
                for (int nt = 0; nt < 4; nt++) {
                    int cb = warp_n * 32 + nt * 8 + 2 * t;
                    float y0 = fmaxf(acc[mt][nt][half * 2 + 0] * sc[nt * 2 + 0] + sh[nt * 2 + 0], 0.f);
                    float y1 = fmaxf(acc[mt][nt][half * 2 + 1] * sc[nt * 2 + 1] + sh[nt * 2 + 1], 0.f);
                    float h0 = y0 + __ldg(vrow + cb);
                    float h1 = y1 + __ldg(vrow + cb + 1);
                    *(float2*)(hin + (size_t)gr * 128 + cb) = make_float2(h0, h1);
                    *(float2*)(agg + (size_t)gr * 128 + cb) = make_float2(ceps * h0, ceps * h1);
                }
            }
        }
}

// ---------------- virtual node ----------------
__global__ void k_vn_agg(const float* __restrict__ hin, const int* __restrict__ batch,
                         const float* __restrict__ vn, float* __restrict__ vt) {
    int g = blockIdx.x, c = threadIdx.x;
    int lo = 0, hi = NN;
    while (lo < hi) { int m = (lo + hi) >> 1; if (batch[m] < g) lo = m + 1; else hi = m; }
    int start = lo;
    lo = start; hi = NN;
    while (lo < hi) { int m = (lo + hi) >> 1; if (batch[m] < g + 1) lo = m + 1; else hi = m; }
    int end = lo;
    float sum = 0.f;
    for (int i = start; i < end; i++) sum += hin[(size_t)i * DD + c];
    vt[g * DD + c] = sum + vn[g * DD + c];
}

__global__ void k_vn_mlp(const float* __restrict__ vt,
                         const float* __restrict__ W1, const float* __restrict__ b1,
                         const float* __restrict__ bn1,
                         const float* __restrict__ W2, const float* __restrict__ b2,
                         const float* __restrict__ bn2, float* __restrict__ vn) {
    __shared__ float xr[DD];
    __shared__ float tr[2 * DD];
    int g = blockIdx.x, tid = threadIdx.x;
    if (tid < DD) xr[tid] = vt[g * DD + tid];
    __syncthreads();
    float acc = b1[tid];
#pragma unroll 8
    for (int k = 0; k < DD; k++) acc = fmaf(xr[k], W1[(size_t)k * 2 * DD + tid], acc);
    float s = bn1[tid] * rsqrtf(bn1[3 * 2 * DD + tid] + BN_EPS);
    acc = (acc - bn1[2 * 2 * DD + tid]) * s + bn1[2 * DD + tid];
    tr[tid] = fmaxf(acc, 0.f);
    __syncthreads();
    if (tid < DD) {
        float a2 = b2[tid];
#pragma unroll 8
        for (int k = 0; k < 2 * DD; k++) a2 = fmaf(tr[k], W2[(size_t)k * DD + tid], a2);
        float s2 = bn2[tid] * rsqrtf(bn2[3 * DD + tid] + BN_EPS);
        a2 = (a2 - bn2[2 * DD + tid]) * s2 + bn2[DD + tid];
        vn[g * DD + tid] = fmaxf(a2, 0.f);
    }
}

// ---------------- host launcher ----------------
extern "C" void kernel_launch(void* const* d_in, const int* in_sizes, int n_in,
                              void* d_out, int out_size) {
    const int*   x_node     = (const int*)d_in[0];
    const int*   edge_index = (const int*)d_in[1];
    const float* edge_attr  = (const float*)d_in[2];
    const int*   batch      = (const int*)d_in[3];
    const int*   pos_index  = (const int*)d_in[4];
    const float* pos_enc    = (const float*)d_in[5];
    const int*   pos_batch  = (const int*)d_in[6];
    const float* node_emb   = (const float*)d_in[7];
    const float* z_init     = (const float*)d_in[8];
    const float* ze_bn1     = (const float*)d_in[9];
    const float* ze_W       = (const float*)d_in[10];
    const float* ze_b       = (const float*)d_in[11];
    const float* ze_bn2     = (const float*)d_in[12];
    const float* vn_emb     = (const float*)d_in[13];
    const float* conv_We    = (const float*)d_in[14];
    const float* conv_be    = (const float*)d_in[15];
    const float* conv_Wp    = (const float*)d_in[16];
    const float* conv_bp    = (const float*)d_in[17];
    const float* conv_W1    = (const float*)d_in[18];
    const float* conv_b1    = (const float*)d_in[19];
    const float* conv_bn    = (const float*)d_in[20];
    const float* conv_W2    = (const float*)d_in[21];
    const float* conv_b2    = (const float*)d_in[22];
    const float* conv_eps   = (const float*)d_in[23];
    const float* layer_bn   = (const float*)d_in[24];
    const float* vn_W1      = (const float*)d_in[25];
    const float* vn_b1      = (const float*)d_in[26];
    const float* vn_bn1     = (const float*)d_in[27];
    const float* vn_W2      = (const float*)d_in[28];
    const float* vn_b2      = (const float*)d_in[29];
    const float* vn_bn2     = (const float*)d_in[30];

    __half *z2, *wph;
    float *hin, *agg, *t2, *vn, *vt, *wh;
    int* sts;
    cudaGetSymbolAddress((void**)&z2,  g_z2);
    cudaGetSymbolAddress((void**)&wph, g_wph);
    cudaGetSymbolAddress((void**)&hin, g_hin);
    cudaGetSymbolAddress((void**)&agg, g_agg);
    cudaGetSymbolAddress((void**)&t2,  g_t2);
    cudaGetSymbolAddress((void**)&vn,  g_vn);
    cudaGetSymbolAddress((void**)&vt,  g_vt);
    cudaGetSymbolAddress((void**)&wh,  g_wh);
    cudaGetSymbolAddress((void**)&sts, g_st);

    cudaFuncSetAttribute(k_zenc, cudaFuncAttributeMaxDynamicSharedMemorySize, SM_BIG);
    cudaFuncSetAttribute(k_edge_fused, cudaFuncAttributeMaxDynamicSharedMemorySize, SM_EDGE);
    cudaFuncSetAttribute(tgemm_w1, cudaFuncAttributeMaxDynamicSharedMemorySize, SM_BIG);
    cudaFuncSetAttribute(tgemm_w2, cudaFuncAttributeMaxDynamicSharedMemorySize, SM_W2);

    float* h = (float*)d_out;

    k_prep<<<1024, 256>>>(ze_W, conv_Wp, conv_W1, conv_W2, wh);
    k_prep16<<<192, 256>>>(conv_Wp, wph);
    k_starts<<<(PP + 256) / 256, 256>>>(pos_batch, sts);
    k_init_vn<<<(GG * DD + 255) / 256, 256>>>(vn_emb, vn);
    k_init_hin<<<(NN * 32 + 255) / 256, 256>>>(x_node, node_emb, vn_emb, conv_eps, hin, agg);
    k_zenc<<<EE / 128, 256, SM_BIG>>>(pos_index, pos_enc, sts, z_init,
                                      ze_bn1, ze_b, ze_bn2, wh + OFF_ZEW, z2);

    const int* srcp = edge_index;
    const int* dstp = edge_index + EE;
    const int nblk = (NN + 127) / 128;

    for (int l = 0; l < LL; l++) {
        k_edge_fused<<<EE / 128, 256, SM_EDGE>>>(z2, wph + l * 16384,
                                                 conv_bp + l * DD, conv_be + l * DD,
                                                 edge_attr, conv_We + (size_t)l * 7 * DD,
                                                 srcp, dstp, hin, agg);
        if (l < LL - 1) {
            k_vn_agg<<<GG, DD>>>(hin, batch, vn, vt);
            k_vn_mlp<<<GG, 256>>>(vt, vn_W1 + (size_t)l * DD * 2 * DD, vn_b1 + l * 2 * DD,
                                  vn_bn1 + (size_t)l * 4 * 2 * DD,
                                  vn_W2 + (size_t)l * 2 * DD * DD, vn_b2 + l * DD,
                                  vn_bn2 + (size_t)l * 4 * DD, vn);
        }
        tgemm_w1<<<dim3(nblk, 2), 256, SM_BIG>>>(agg, wh + OFF_W1(l),
                                                 NN, conv_b1 + l * 2 * DD,
                                                 conv_bn + (size_t)l * 4 * 2 * DD, t2);
        int fin = (l == LL - 1) ? 1 : 0;
        tgemm_w2<<<dim3(nblk, 1), 256, SM_W2>>>(t2, wh + OFF_W2(l),
                                                NN, conv_b2 + l * DD,
                                                layer_bn + (size_t)l * 4 * DD,
                                                fin, h, vn, batch,
                                                conv_eps + (fin ? l : l + 1),
                                                hin, agg);
    }
}

// round 17
// speedup vs baseline: 1.2556x; 1.0014x over previous
#include <cuda_runtime.h>
#include <cuda_fp16.h>
#include <cstddef>
#include <cstdint>

#define NN 100000
#define EE 640000
#define PP 640000
#define DD 128
#define GG 128
#define LL 3
#define BN_EPS 1e-5f

// ---------------- device scratch ----------------
__device__ __half g_z2 [(size_t)EE * DD];            // fp16 z after encoder
__device__ float  g_hin[(size_t)NN * DD];            // fp32
__device__ float  g_agg[(size_t)NN * DD];            // fp32 (atomic target)
__device__ float  g_t2 [((size_t)NN + 128) * 2 * DD];// tf32-rounded fp32 (+pad)
__device__ float  g_vn [GG * DD];
__device__ float  g_vt [GG * DD];
__device__ float  g_wh [262144];                     // tf32-rounded weights
__device__ __half g_wph[49152];                      // fp16 n-major Wp (3 layers)
__device__ int    g_st [EE + 1];                     // pos_batch segment starts

#define OFF_ZEW 0
#define OFF_WP(l) (16384 + (l) * 81920)
#define OFF_W1(l) (16384 + (l) * 81920 + 16384)
#define OFF_W2(l) (16384 + (l) * 81920 + 49152)

// ---------------- helpers ----------------
__device__ __forceinline__ void red_add_v4(float* p, float4 v) {
    asm volatile("red.global.add.v4.f32 [%0], {%1,%2,%3,%4};"
                 :: "l"(p), "f"(v.x), "f"(v.y), "f"(v.z), "f"(v.w) : "memory");
}
__device__ __forceinline__ unsigned f2tf(float f) {
    unsigned u;
    asm("cvt.rna.tf32.f32 %0, %1;" : "=r"(u) : "f"(f));
    return u;
}
__device__ __forceinline__ float tf32r(float f) { return __uint_as_float(f2tf(f)); }
__device__ __forceinline__ void mma_tf32(float* c, const unsigned* a, const unsigned* b) {
    asm volatile("mma.sync.aligned.m16n8k8.row.col.f32.tf32.tf32.f32 "
                 "{%0,%1,%2,%3}, {%4,%5,%6,%7}, {%8,%9}, {%0,%1,%2,%3};"
                 : "+f"(c[0]), "+f"(c[1]), "+f"(c[2]), "+f"(c[3])
                 : "r"(a[0]), "r"(a[1]), "r"(a[2]), "r"(a[3]),
                   "r"(b[0]), "r"(b[1]));
}
__device__ __forceinline__ void mma_f16(float* c, const unsigned* a, const unsigned* b) {
    asm volatile("mma.sync.aligned.m16n8k16.row.col.f32.f16.f16.f32 "
                 "{%0,%1,%2,%3},{%4,%5,%6,%7},{%8,%9},{%0,%1,%2,%3};"
                 : "+f"(c[0]), "+f"(c[1]), "+f"(c[2]), "+f"(c[3])
                 : "r"(a[0]), "r"(a[1]), "r"(a[2]), "r"(a[3]), "r"(b[0]), "r"(b[1]));
}
__device__ __forceinline__ unsigned pack2h(float x, float y) {
    __half2 h = __floats2half2_rn(x, y);
    return *(unsigned*)&h;
}
__device__ __forceinline__ void cp16(void* s, const void* g) {
    unsigned sa = (unsigned)__cvta_generic_to_shared(s);
    asm volatile("cp.async.cg.shared.global [%0], [%1], 16;" :: "r"(sa), "l"(g));
}
__device__ __forceinline__ void cp_commit() {
    asm volatile("cp.async.commit_group;" ::: "memory");
}
__device__ __forceinline__ void cp_wait0() {
    asm volatile("cp.async.wait_group 0;" ::: "memory");
}

#define AS_S 68
#define BS_S 132
#define SM_BIG ((128 * AS_S + 128 * BS_S) * 4)   // 102400 B (zenc / W1)
#define SM_W2  ((128 * AS_S + 64 * BS_S) * 4)    // 68608 B
#define SH2 136                                  // halves per row, fp16 tiles
#define SM_EDGE (2 * 128 * SH2 * 2)              // 69632 B : As + Bs fp16

#define MMA_CHUNK(As, Bs, warp_m, warp_n, g, t, acc)                               \
    _Pragma("unroll")                                                              \
    for (int kk = 0; kk < 64; kk += 8) {                                           \
        unsigned af[4][4], bf[4][2];                                               \
        _Pragma("unroll")                                                          \
        for (int mt = 0; mt < 4; mt++) {                                           \
            int mb = (warp_m) * 64 + mt * 16;                                      \
            af[mt][0] = (As)[(mb + (g)) * AS_S + kk + (t)];                        \
            af[mt][1] = (As)[(mb + (g) + 8) * AS_S + kk + (t)];                    \
            af[mt][2] = (As)[(mb + (g)) * AS_S + kk + (t) + 4];                    \
            af[mt][3] = (As)[(mb + (g) + 8) * AS_S + kk + (t) + 4];                \
        }                                                                          \
        _Pragma("unroll")                                                          \
        for (int nt = 0; nt < 4; nt++) {                                           \
            int n = (warp_n) * 32 + nt * 8 + (g);                                  \
            bf[nt][0] = (Bs)[(kk + (t)) * BS_S + n];                               \
            bf[nt][1] = (Bs)[(kk + (t) + 4) * BS_S + n];                           \
        }                                                                          \
        _Pragma("unroll")                                                          \
        for (int mt = 0; mt < 4; mt++)                                             \
            _Pragma("unroll")                                                      \
            for (int nt = 0; nt < 4; nt++)                                         \
                mma_tf32(acc[mt][nt], af[mt], bf[nt]);                             \
    }

// ---------------- prep kernels ----------------
__global__ void k_prep(const float* __restrict__ zeW, const float* __restrict__ Wp,
                       const float* __restrict__ W1, const float* __restrict__ W2,
                       float* __restrict__ wh) {
    int i = blockIdx.x * 256 + threadIdx.x;
    if (i >= 262144) return;
    if (i < 16384) { wh[OFF_ZEW + i] = tf32r(zeW[i]); return; }
    int j = i - 16384;
    int l = j / 81920;
    j = j % 81920;
    if (j < 16384)       wh[OFF_WP(l) + j]           = tf32r(Wp[(size_t)l * 16384 + j]);
    else if (j < 49152)  wh[OFF_W1(l) + (j - 16384)] = tf32r(W1[(size_t)l * 32768 + j - 16384]);
    else                 wh[OFF_W2(l) + (j - 49152)] = tf32r(W2[(size_t)l * 32768 + j - 49152]);
}

// fp16 n-major Wp for fp16 MMA: wph[l][n][k] = Wp[l][k][n]
__global__ void k_prep16(const float* __restrict__ Wp, __half* __restrict__ wph) {
    int i = blockIdx.x * 256 + threadIdx.x;
    if (i >= 49152) return;
    int l = i / 16384;
    int j = i % 16384;
    int n = j >> 7, k = j & 127;
    wph[i] = __float2half(Wp[(size_t)l * 16384 + k * 128 + n]);
}

__global__ void k_starts(const int* __restrict__ pbatch, int* __restrict__ starts) {
    int p = blockIdx.x * 256 + threadIdx.x;
    if (p > PP) return;
    int prev = (p == 0) ? -1 : __ldg(pbatch + p - 1);
    int cur  = (p == PP) ? EE : __ldg(pbatch + p);
    for (int seg = prev + 1; seg <= cur; seg++) starts[seg] = p;
}

// ---------------- init kernels ----------------
__global__ void k_init_vn(const float* __restrict__ emb, float* __restrict__ vn) {
    int i = blockIdx.x * blockDim.x + threadIdx.x;
    if (i < GG * DD) vn[i] = emb[i & (DD - 1)];
}

__global__ void k_init_hin(const int* __restrict__ xn, const float* __restrict__ emb,
                           const float* __restrict__ vne, const float* __restrict__ epsp,
                           float* __restrict__ hin, float* __restrict__ agg) {
    int i = blockIdx.x * blockDim.x + threadIdx.x;
    if (i >= NN * 32) return;
    int row = i >> 5, q = (i & 31) << 2;
    float c = 1.0f + __ldg(epsp);
    float4 a = *(const float4*)(emb + (size_t)xn[row] * DD + q);
    float4 b = *(const float4*)(vne + q);
    a.x += b.x; a.y += b.y; a.z += b.z; a.w += b.w;
    *(float4*)(hin + (size_t)row * DD + q) = a;
    float4 e = make_float4(c * a.x, c * a.y, c * a.z, c * a.w);
    *(float4*)(agg + (size_t)row * DD + q) = e;
}

// ---------------- fused z-encoder (tf32, RNA cvt) ----------------
__global__ __launch_bounds__(256, 2)
void k_zenc(const int* __restrict__ pidx, const float* __restrict__ penc,
            const int* __restrict__ startsg, const float* __restrict__ zinit,
            const float* __restrict__ bn1, const float* __restrict__ zeb,
            const float* __restrict__ bn2, const float* __restrict__ zeWr,
            __half* __restrict__ z2) {
    extern __shared__ unsigned smem[];
    unsigned* As = smem;
    unsigned* Bs = smem + 128 * AS_S;
    __shared__ float sc1[128], sh1[128];

    const int tid = threadIdx.x;
    const int row0 = blockIdx.x * 128;

#pragma unroll
    for (int i = 0; i < 16; i++) {
        int idx = tid + i * 256;
        int r = idx >> 5, c4 = (idx & 31) << 2;
        cp16(Bs + r * BS_S + c4, zeWr + r * 128 + c4);
    }
    cp_commit();

    if (tid < 128) {
        float s = bn1[tid] * rsqrtf(bn1[3 * 128 + tid] + BN_EPS);
        sc1[tid] = s;
        sh1[tid] = bn1[128 + tid] - bn1[2 * 128 + tid] * s;
    }
    __syncthreads();

    const int lane = tid & 31, wid = tid >> 5;
    const int g = lane >> 2, t = lane & 3;
    const int warp_m = wid & 1, warp_n = wid >> 1;
    const int ar = tid >> 1;

    float acc[4][4][4];
#pragma unroll
    for (int mt = 0; mt < 4; mt++)
#pragma unroll
        for (int nt = 0; nt < 4; nt++)
#pragma unroll
            for (int q = 0; q < 4; q++) acc[mt][nt][q] = 0.f;

    const int st = __ldg(startsg + row0 + ar);
    const int en = __ldg(startsg + row0 + ar + 1);

    for (int k0 = 0; k0 < 128; k0 += 64) {
#pragma unroll
        for (int sub = 0; sub < 2; sub++) {
            int cc = (tid & 1) * 32 + sub * 16;
            float4 a[4];
#pragma unroll
            for (int j = 0; j < 4; j++) a[j] = make_float4(0.f, 0.f, 0.f, 0.f);
            for (int p = st; p < en; p++) {
                int zi = __ldg(pidx + p);
                float w = __ldg(penc + p);
                const float* zr = zinit + (size_t)zi * 128 + k0 + cc;
#pragma unroll
                for (int j = 0; j < 4; j++) {
                    float4 v = *(const float4*)(zr + 4 * j);
                    a[j].x += v.x * w; a[j].y += v.y * w; a[j].z += v.z * w; a[j].w += v.w * w;
                }
            }
#pragma unroll
            for (int j = 0; j < 4; j++) {
                int c = cc + 4 * j;
                int gc = k0 + c;
                float y0 = fmaxf(a[j].x * sc1[gc + 0] + sh1[gc + 0], 0.f);
                float y1 = fmaxf(a[j].y * sc1[gc + 1] + sh1[gc + 1], 0.f);
                float y2 = fmaxf(a[j].z * sc1[gc + 2] + sh1[gc + 2], 0.f);
                float y3 = fmaxf(a[j].w * sc1[gc + 3] + sh1[gc + 3], 0.f);
                *(uint4*)(As + ar * AS_S + c) = make_uint4(f2tf(y0), f2tf(y1), f2tf(y2), f2tf(y3));
            }
        }
        if (k0 == 0) cp_wait0();
        __syncthreads();
        MMA_CHUNK(As, Bs + k0 * BS_S, warp_m, warp_n, g, t, acc)
        __syncthreads();
    }

    float sc[8], sh[8];
#pragma unroll
    for (int nt = 0; nt < 4; nt++)
#pragma unroll
        for (int hh = 0; hh < 2; hh++) {
            int c = warp_n * 32 + nt * 8 + 2 * t + hh;
            float s = bn2[c] * rsqrtf(bn2[3 * 128 + c] + BN_EPS);
            sc[nt * 2 + hh] = s;
            sh[nt * 2 + hh] = bn2[128 + c] + (zeb[c] - bn2[2 * 128 + c]) * s;
        }
#pragma unroll
    for (int mt = 0; mt < 4; mt++)
#pragma unroll
        for (int half = 0; half < 2; half++) {
            int gr = row0 + warp_m * 64 + mt * 16 + g + 8 * half;
#pragma unroll
            for (int nt = 0; nt < 4; nt++) {
                float y0 = fmaxf(acc[mt][nt][half * 2 + 0] * sc[nt * 2 + 0] + sh[nt * 2 + 0], 0.f);
                float y1 = fmaxf(acc[mt][nt][half * 2 + 1] * sc[nt * 2 + 1] + sh[nt * 2 + 1], 0.f);
                int cb = warp_n * 32 + nt * 8 + 2 * t;
                *(unsigned*)(z2 + (size_t)gr * 128 + cb) = pack2h(y0, y1);
            }
        }
}

// ---------------- fused edge GEMM (fp16 MMA) + gather + scatter ----------------
__global__ __launch_bounds__(256, 2)
void k_edge_fused(const __half* __restrict__ z2, const __half* __restrict__ Wph,
                  const float* __restrict__ bp, const float* __restrict__ be,
                  const float* __restrict__ Ae, const float* __restrict__ We7,
                  const int* __restrict__ src, const int* __restrict__ dst,
                  const float* __restrict__ hin, float* __restrict__ agg) {
    extern __shared__ __half hsm[];
    __half* As = hsm;
    __half* Bs = hsm + 128 * SH2;
    float* eeS = (float*)hsm;            // [128][132], aliases As/Bs
    __shared__ float AeS[128 * 8];
    __shared__ float WeS[7 * 128];

    const int tid = threadIdx.x;
    const int row0 = blockIdx.x * 128;

#pragma unroll
    for (int i = 0; i < 8; i++) {
        int idx = tid + i * 256;
        int r = idx >> 4, c8 = (idx & 15) << 3;
        cp16(As + r * SH2 + c8, z2 + (size_t)(row0 + r) * 128 + c8);
        cp16(Bs + r * SH2 + c8, Wph + r * 128 + c8);
    }
    cp_commit();

    for (int i = tid; i < 128 * 7; i += 256) {
        int r = i / 7, c = i % 7;
        AeS[r * 8 + c] = Ae[(size_t)(row0 + r) * 7 + c];
    }
    for (int i = tid; i < 7 * 128; i += 256) WeS[i] = We7[i];

    const int lane = tid & 31, wid = tid >> 5;
    const int g = lane >> 2, t = lane & 3;
    const int warp_m = wid & 1, warp_n = wid >> 1;

    float acc[4][4][4];
#pragma unroll
    for (int mt = 0; mt < 4; mt++)
#pragma unroll
        for (int nt = 0; nt < 4; nt++)
#pragma unroll
            for (int q = 0; q < 4; q++) acc[mt][nt][q] = 0.f;

    cp_wait0();
    __syncthreads();

#pragma unroll
    for (int kk = 0; kk < 128; kk += 16) {
        unsigned af[4][4], bf[4][2];
#pragma unroll
        for (int mt = 0; mt < 4; mt++) {
            const __half* pa = As + (warp_m * 64 + mt * 16 + g) * SH2 + kk + 2 * t;
            af[mt][0] = *(const unsigned*)pa;
            af[mt][1] = *(const unsigned*)(pa + 8 * SH2);
            af[mt][2] = *(const unsigned*)(pa + 8);
            af[mt][3] = *(const unsigned*)(pa + 8 * SH2 + 8);
        }
#pragma unroll
        for (int nt = 0; nt < 4; nt++) {
            const __half* pb = Bs + (warp_n * 32 + nt * 8 + g) * SH2 + kk + 2 * t;
            bf[nt][0] = *(const unsigned*)pb;
            bf[nt][1] = *(const unsigned*)(pb + 8);
        }
#pragma unroll
        for (int mt = 0; mt < 4; mt++)
#pragma unroll
            for (int nt = 0; nt < 4; nt++)
                mma_f16(acc[mt][nt], af[mt], bf[nt]);
    }
    __syncthreads();   // all warps done reading As/Bs before aliasing as eeS

    float bsum[8];
#pragma unroll
    for (int nt = 0; nt < 4; nt++)
#pragma unroll
        for (int hh = 0; hh < 2; hh++) {
            int c = warp_n * 32 + nt * 8 + 2 * t + hh;
            bsum[nt * 2 + hh] = bp[c] + be[c];
        }
#pragma unroll
    for (int mt = 0; mt < 4; mt++)
#pragma unroll
        for (int half = 0; half < 2; half++) {
            int lr = warp_m * 64 + mt * 16 + g + 8 * half;
            float a7[7];
#pragma unroll
            for (int k = 0; k < 7; k++) a7[k] = AeS[lr * 8 + k];
#pragma unroll
            for (int nt = 0; nt < 4; nt++) {
                int cb = warp_n * 32 + nt * 8 + 2 * t;
                float y0 = acc[mt][nt][half * 2 + 0] + bsum[nt * 2 + 0];
                float y1 = acc[mt][nt][half * 2 + 1] + bsum[nt * 2 + 1];
#pragma unroll
                for (int k = 0; k < 7; k++) {
                    y0 = fmaf(a7[k], WeS[k * 128 + cb], y0);
                    y1 = fmaf(a7[k], WeS[k * 128 + cb + 1], y1);
                }
                *(float2*)(eeS + lr * 132 + cb) = make_float2(y0, y1);
            }
        }
    __syncthreads();

    // gather + relu + scatter: warp per edge
#pragma unroll 4
    for (int i = 0; i < 16; i++) {
        int lr = wid * 16 + i;
        int e = row0 + lr;
        int s = __ldg(src + e), d = __ldg(dst + e);
        float4 ev = *(float4*)(eeS + lr * 132 + lane * 4);
        float4 hv = *(const float4*)(hin + (size_t)s * 128 + lane * 4);
        float4 m;
        m.x = fmaxf(hv.x + ev.x, 0.f);
        m.y = fmaxf(hv.y + ev.y, 0.f);
        m.z = fmaxf(hv.z + ev.z, 0.f);
        m.w = fmaxf(hv.w + ev.w, 0.f);
        red_add_v4(agg + (size_t)d * 128 + lane * 4, m);
    }
}

// ---------------- W1 GEMM (tf32, RNA cvt): t2 = tf32r(relu(bn(agg @ W1 + b1))) ----------------
__global__ __launch_bounds__(256, 2)
void tgemm_w1(const float* __restrict__ A, const float* __restrict__ W1r,
              int M, const float* __restrict__ bias, const float* __restrict__ bn,
              float* __restrict__ C) {
    extern __shared__ unsigned smem[];
    unsigned* As = smem;
    unsigned* Bs = smem + 128 * AS_S;
    const int tid = threadIdx.x;
    const int lane = tid & 31, wid = tid >> 5;
    const int g = lane >> 2, t = lane & 3;
    const int warp_m = wid & 1, warp_n = wid >> 1;
    const int row0 = blockIdx.x * 128;
    const int col0 = blockIdx.y * 128;
    const int arow = tid >> 4, acol = (tid & 15) << 2;
    const int Nc = 256;

#pragma unroll
    for (int i = 0; i < 16; i++) {
        int idx = tid + i * 256;
        int r = idx >> 5, c4 = (idx & 31) << 2;
        cp16(Bs + r * BS_S + c4, W1r + (size_t)r * Nc + col0 + c4);
    }
    cp_commit();

    float acc[4][4][4];
#pragma unroll
    for (int mt = 0; mt < 4; mt++)
#pragma unroll
        for (int nt = 0; nt < 4; nt++)
#pragma unroll
            for (int q = 0; q < 4; q++) acc[mt][nt][q] = 0.f;

    for (int k0 = 0; k0 < 128; k0 += 64) {
        __syncthreads();
#pragma unroll
        for (int p = 0; p < 8; p++) {
            int r = arow + p * 16;
            int gr = row0 + r;
            float4 v = make_float4(0.f, 0.f, 0.f, 0.f);
            if (gr < M) v = *(const float4*)(A + (size_t)gr * 128 + k0 + acol);
            *(uint4*)(As + r * AS_S + acol) = make_uint4(f2tf(v.x), f2tf(v.y), f2tf(v.z), f2tf(v.w));
        }
        if (k0 == 0) cp_wait0();
        __syncthreads();
        MMA_CHUNK(As, Bs + k0 * BS_S, warp_m, warp_n, g, t, acc)
    }

    float sc[8], sh[8];
#pragma unroll
    for (int nt = 0; nt < 4; nt++)
#pragma unroll
        for (int hh = 0; hh < 2; hh++) {
            int c = col0 + warp_n * 32 + nt * 8 + 2 * t + hh;
            float s = bn[c] * rsqrtf(bn[3 * Nc + c] + BN_EPS);
            sc[nt * 2 + hh] = s;
            sh[nt * 2 + hh] = bn[Nc + c] + (bias[c] - bn[2 * Nc + c]) * s;
        }
#pragma unroll
    for (int mt = 0; mt < 4; mt++)
#pragma unroll
        for (int half = 0; half < 2; half++) {
            int gr = row0 + warp_m * 64 + mt * 16 + g + 8 * half;
            if (gr >= M) continue;
#pragma unroll
            for (int nt = 0; nt < 4; nt++) {
                float y0 = fmaxf(acc[mt][nt][half * 2 + 0] * sc[nt * 2 + 0] + sh[nt * 2 + 0], 0.f);
                float y1 = fmaxf(acc[mt][nt][half * 2 + 1] * sc[nt * 2 + 1] + sh[nt * 2 + 1], 0.f);
                int cb = warp_n * 32 + nt * 8 + 2 * t;
                *(float2*)(C + (size_t)gr * Nc + col0 + cb) = make_float2(tf32r(y0), tf32r(y1));
            }
        }
}

// ---------------- W2 GEMM (tf32, RNA; t2 pre-rounded, cp.async) + fused next-layer epilogue ----------------
__global__ __launch_bounds__(256, 2)
void tgemm_w2(const float* __restrict__ A, const float* __restrict__ W2r,
              int M, const float* __restrict__ bias, const float* __restrict__ bn,
              int final_, float* __restrict__ Cf,
              const float* __restrict__ vnext, const int* __restrict__ batch,
              const float* __restrict__ epsp,
              float* __restrict__ hin, float* __restrict__ agg) {
    extern __shared__ unsigned smem[];
    unsigned* As = smem;
    unsigned* Bs = smem + 128 * AS_S;
    const int tid = threadIdx.x;
    const int lane = tid & 31, wid = tid >> 5;
    const int g = lane >> 2, t = lane & 3;
    const int warp_m = wid & 1, warp_n = wid >> 1;
    const int row0 = blockIdx.x * 128;

    float acc[4][4][4];
#pragma unroll
    for (int mt = 0; mt < 4; mt++)
#pragma unroll
        for (int nt = 0; nt < 4; nt++)
#pragma unroll
            for (int q = 0; q < 4; q++) acc[mt][nt][q] = 0.f;

    for (int k0 = 0; k0 < 256; k0 += 64) {
        __syncthreads();
#pragma unroll
        for (int i = 0; i < 8; i++) {
            int idx = tid + i * 256;
            int r = idx >> 4, c4 = (idx & 15) << 2;
            cp16(As + r * AS_S + c4, A + (size_t)(row0 + r) * 256 + k0 + c4);
        }
#pragma unroll
        for (int i = 0; i < 8; i++) {
            int idx = tid + i * 256;
            int r = idx >> 5, c4 = (idx & 31) << 2;
            cp16(Bs + r * BS_S + c4, W2r + (size_t)(k0 + r) * 128 + c4);
        }
        cp_commit();
        cp_wait0();
        __syncthreads();
        MMA_CHUNK(As, Bs, warp_m, warp_n, g, t, acc)
    }

    float sc[8], sh[8];
#pragma unroll
    for (int nt = 0; nt < 4; nt++)
#pragma unroll
        for (int hh = 0; hh < 2; hh++) {
            int c = warp_n * 32 + nt * 8 + 2 * t + hh;
            float s = bn[c] * rsqrtf(bn[3 * 128 + c] + BN_EPS);
            sc[nt * 2 + hh] = s;
            sh[nt * 2 + hh] = bn[128 + c] + (bias[c] - bn[2 * 128 + c]) * s;
        }

    float ceps = final_ ? 0.f : (1.0f + __ldg(epsp));
#pragma unroll
    for (int mt = 0; mt < 4; mt++)
#pragma unroll
        for (int half = 0; half < 2; half++) {
            int gr = row0 + warp_m * 64 + mt * 16 + g + 8 * half;
            if (gr >= M) continue;
            if (final_) {
#pragma unroll
                for (int nt = 0; nt < 4; nt++) {
                    float y0 = acc[mt][nt][half * 2 + 0] * sc[nt * 2 + 0] + sh[nt * 2 + 0];
                    float y1 = acc[mt][nt][half * 2 + 1] * sc[nt * 2 + 1] + sh[nt * 2 + 1];
                    int cb = warp_n * 32 + nt * 8 + 2 * t;
                    *(float2*)(Cf + (size_t)gr * 128 + cb) = make_float2(y0, y1);
                }
            } else {
                int b = __ldg(batch + gr);
                const float* vrow = vnext + (size_t)b * 128;
#pragma unroll
                for (int nt = 0; nt < 4; nt++) {
                    int cb = warp_n * 32 + nt * 8 + 2 * t;
                    float y0 = fmaxf(acc[mt][nt][half * 2 + 0] * sc[nt * 2 + 0] + sh[nt * 2 + 0], 0.f);
                    float y1 = fmaxf(acc[mt][nt][half * 2 + 1] * sc[nt * 2 + 1] + sh[nt * 2 + 1], 0.f);
                    float h0 = y0 + __ldg(vrow + cb);
                    float h1 = y1 + __ldg(vrow + cb + 1);
                    *(float2*)(hin + (size_t)gr * 128 + cb) = make_float2(h0, h1);
                    *(float2*)(agg + (size_t)gr * 128 + cb) = make_float2(ceps * h0, ceps * h1);
                }
            }
        }
}

// ---------------- virtual node ----------------
__global__ void k_vn_agg(const float* __restrict__ hin, const int* __restrict__ batch,
                         const float* __restrict__ vn, float* __restrict__ vt) {
    int g = blockIdx.x, c = threadIdx.x;
    int lo = 0, hi = NN;
    while (lo < hi) { int m = (lo + hi) >> 1; if (batch[m] < g) lo = m + 1; else hi = m; }
    int start = lo;
    lo = start; hi = NN;
    while (lo < hi) { int m = (lo + hi) >> 1; if (batch[m] < g + 1) lo = m + 1; else hi = m; }
    int end = lo;
    float sum = 0.f;
    for (int i = start; i < end; i++) sum += hin[(size_t)i * DD + c];
    vt[g * DD + c] = sum + vn[g * DD + c];
}

__global__ void k_vn_mlp(const float* __restrict__ vt,
                         const float* __restrict__ W1, const float* __restrict__ b1,
                         const float* __restrict__ bn1,
                         const float* __restrict__ W2, const float* __restrict__ b2,
                         const float* __restrict__ bn2, float* __restrict__ vn) {
    __shared__ float xr[DD];
    __shared__ float tr[2 * DD];
    int g = blockIdx.x, tid = threadIdx.x;
    if (tid < DD) xr[tid] = vt[g * DD + tid];
    __syncthreads();
    float acc = b1[tid];
#pragma unroll 8
    for (int k = 0; k < DD; k++) acc = fmaf(xr[k], W1[(size_t)k * 2 * DD + tid], acc);
    float s = bn1[tid] * rsqrtf(bn1[3 * 2 * DD + tid] + BN_EPS);
    acc = (acc - bn1[2 * 2 * DD + tid]) * s + bn1[2 * DD + tid];
    tr[tid] = fmaxf(acc, 0.f);
    __syncthreads();
    if (tid < DD) {
        float a2 = b2[tid];
#pragma unroll 8
        for (int k = 0; k < 2 * DD; k++) a2 = fmaf(tr[k], W2[(size_t)k * DD + tid], a2);
        float s2 = bn2[tid] * rsqrtf(bn2[3 * DD + tid] + BN_EPS);
        a2 = (a2 - bn2[2 * DD + tid]) * s2 + bn2[DD + tid];
        vn[g * DD + tid] = fmaxf(a2, 0.f);
    }
}

// ---------------- host launcher ----------------
extern "C" void kernel_launch(void* const* d_in, const int* in_sizes, int n_in,
                              void* d_out, int out_size) {
    const int*   x_node     = (const int*)d_in[0];
    const int*   edge_index = (const int*)d_in[1];
    const float* edge_attr  = (const float*)d_in[2];
    const int*   batch      = (const int*)d_in[3];
    const int*   pos_index  = (const int*)d_in[4];
    const float* pos_enc    = (const float*)d_in[5];
    const int*   pos_batch  = (const int*)d_in[6];
    const float* node_emb   = (const float*)d_in[7];
    const float* z_init     = (const float*)d_in[8];
    const float* ze_bn1     = (const float*)d_in[9];
    const float* ze_W       = (const float*)d_in[10];
    const float* ze_b       = (const float*)d_in[11];
    const float* ze_bn2     = (const float*)d_in[12];
    const float* vn_emb     = (const float*)d_in[13];
    const float* conv_We    = (const float*)d_in[14];
    const float* conv_be    = (const float*)d_in[15];
    const float* conv_Wp    = (const float*)d_in[16];
    const float* conv_bp    = (const float*)d_in[17];
    const float* conv_W1    = (const float*)d_in[18];
    const float* conv_b1    = (const float*)d_in[19];
    const float* conv_bn    = (const float*)d_in[20];
    const float* conv_W2    = (const float*)d_in[21];
    const float* conv_b2    = (const float*)d_in[22];
    const float* conv_eps   = (const float*)d_in[23];
    const float* layer_bn   = (const float*)d_in[24];
    const float* vn_W1      = (const float*)d_in[25];
    const float* vn_b1      = (const float*)d_in[26];
    const float* vn_bn1     = (const float*)d_in[27];
    const float* vn_W2      = (const float*)d_in[28];
    const float* vn_b2      = (const float*)d_in[29];
    const float* vn_bn2     = (const float*)d_in[30];

    __half *z2, *wph;
    float *hin, *agg, *t2, *vn, *vt, *wh;
    int* sts;
    cudaGetSymbolAddress((void**)&z2,  g_z2);
    cudaGetSymbolAddress((void**)&wph, g_wph);
    cudaGetSymbolAddress((void**)&hin, g_hin);
    cudaGetSymbolAddress((void**)&agg, g_agg);
    cudaGetSymbolAddress((void**)&t2,  g_t2);
    cudaGetSymbolAddress((void**)&vn,  g_vn);
    cudaGetSymbolAddress((void**)&vt,  g_vt);
    cudaGetSymbolAddress((void**)&wh,  g_wh);
    cudaGetSymbolAddress((void**)&sts, g_st);

    cudaFuncSetAttribute(k_zenc, cudaFuncAttributeMaxDynamicSharedMemorySize, SM_BIG);
    cudaFuncSetAttribute(k_edge_fused, cudaFuncAttributeMaxDynamicSharedMemorySize, SM_EDGE);
    cudaFuncSetAttribute(tgemm_w1, cudaFuncAttributeMaxDynamicSharedMemorySize, SM_BIG);
    cudaFuncSetAttribute(tgemm_w2, cudaFuncAttributeMaxDynamicSharedMemorySize, SM_W2);

    float* h = (float*)d_out;

    k_prep<<<1024, 256>>>(ze_W, conv_Wp, conv_W1, conv_W2, wh);
    k_prep16<<<192, 256>>>(conv_Wp, wph);
    k_starts<<<(PP + 256) / 256, 256>>>(pos_batch, sts);
    k_init_vn<<<(GG * DD + 255) / 256, 256>>>(vn_emb, vn);
    k_init_hin<<<(NN * 32 + 255) / 256, 256>>>(x_node, node_emb, vn_emb, conv_eps, hin, agg);
    k_zenc<<<EE / 128, 256, SM_BIG>>>(pos_index, pos_enc, sts, z_init,
                                      ze_bn1, ze_b, ze_bn2, wh + OFF_ZEW, z2);

    const int* srcp = edge_index;
    const int* dstp = edge_index + EE;
    const int nblk = (NN + 127) / 128;

    for (int l = 0; l < LL; l++) {
        k_edge_fused<<<EE / 128, 256, SM_EDGE>>>(z2, wph + l * 16384,
                                                 conv_bp + l * DD, conv_be + l * DD,
                                                 edge_attr, conv_We + (size_t)l * 7 * DD,
                                                 srcp, dstp, hin, agg);
        if (l < LL - 1) {
            k_vn_agg<<<GG, DD>>>(hin, batch, vn, vt);
            k_vn_mlp<<<GG, 256>>>(vt, vn_W1 + (size_t)l * DD * 2 * DD, vn_b1 + l * 2 * DD,
                                  vn_bn1 + (size_t)l * 4 * 2 * DD,
                                  vn_W2 + (size_t)l * 2 * DD * DD, vn_b2 + l * DD,
                                  vn_bn2 + (size_t)l * 4 * DD, vn);
        }
        tgemm_w1<<<dim3(nblk, 2), 256, SM_BIG>>>(agg, wh + OFF_W1(l),
                                                 NN, conv_b1 + l * 2 * DD,
                                                 conv_bn + (size_t)l * 4 * 2 * DD, t2);
        int fin = (l == LL - 1) ? 1 : 0;
        tgemm_w2<<<dim3(nblk, 1), 256, SM_W2>>>(t2, wh + OFF_W2(l),
                                                NN, conv_b2 + l * DD,
                                                layer_bn + (size_t)l * 4 * DD,
                                                fin, h, vn, batch,
                                                conv_eps + (fin ? l : l + 1),
                                                hin, agg);
    }
}